// round 15
// baseline (speedup 1.0000x reference)
#include <cuda_runtime.h>
#include <cuda_bf16.h>
#include <cuda_fp16.h>
#include <math.h>
#include <stdint.h>

#define BT 2
#define CC 128
#define HH 128
#define WW 128
#define HS 64
#define NP 4096
#define K1 1152
#define HWF 16384
#define SCALEF 10.0f
#define SEL_THR 1e-7f
#define SLOTS 24
#define KMAX 128
#define CWIN 16.2f

// ===================== scratch =====================
__device__ __align__(256) __nv_bfloat16 g_bh [(size_t)BT*NP*CC];
__device__ __align__(256) __nv_bfloat16 g_bl [(size_t)BT*NP*CC];
__device__ __align__(256) __nv_bfloat16 g_fh [(size_t)BT*NP*CC];
__device__ __align__(256) __nv_bfloat16 g_fl [(size_t)BT*NP*CC];
__device__ __align__(256) __half        g_bgcl[(size_t)BT*HWF*CC]; // bg channels-last fp16
__device__ __align__(256) __half        g_y16 [(size_t)BT*HWF*CC]; // y image channels-last
__device__ __align__(256) __half        g_h16 [(size_t)BT*HWF*CC]; // h image channels-last
__device__ __align__(256) __half        g_w116[CC*K1];
__device__ __align__(256) __half        g_w216[CC*K1];
__device__ __align__(256) float g_bufA[(size_t)BT*NP*NP];
__device__ __align__(256) float g_bufB[(size_t)BT*NP*NP];
__device__ int   g_cidx[(size_t)BT*NP*32*SLOTS];   // candidate row idx
__device__ float g_clog[(size_t)BT*NP*32*SLOTS];   // candidate logit (exact fp32)
__device__ int   g_ccnt[BT*NP*32];
__device__ int   g_midx[(size_t)BT*NP*KMAX];
__device__ float g_mwgt[(size_t)BT*NP*KMAX];
__device__ int   g_mcnt[BT*NP];
__device__ float g_eq  [NP];
__device__ float g_ss  [BT*NP];
__device__ float g_inv [BT*NP];
__device__ float g_pmax[BT*32*NP];
__device__ float g_psum[BT*32*NP];
__device__ float g_cmax[BT*NP];
__device__ float g_csum[BT*NP];
__device__ float g_lthr[BT*NP];

__device__ __forceinline__ void split_store(__nv_bfloat16* H, __nv_bfloat16* L,
                                            size_t idx, float v) {
    __nv_bfloat16 h = __float2bfloat16(v);
    H[idx] = h;
    L[idx] = __float2bfloat16(v - __bfloat162float(h));
}
__device__ __forceinline__ uint32_t smem_u32(const void* p) {
    uint32_t a;
    asm("{ .reg .u64 t; cvta.to.shared.u64 t, %1; cvt.u32.u64 %0, t; }" : "=r"(a) : "l"(p));
    return a;
}
__device__ __forceinline__ void ldsm_x4(uint32_t (&r)[4], uint32_t addr) {
    asm volatile("ldmatrix.sync.aligned.m8n8.x4.shared.b16 {%0,%1,%2,%3}, [%4];"
                 : "=r"(r[0]), "=r"(r[1]), "=r"(r[2]), "=r"(r[3]) : "r"(addr));
}
__device__ __forceinline__ void mma_bf16(float (&d)[4], const uint32_t (&a)[4],
                                         uint32_t b0, uint32_t b1) {
    asm volatile("mma.sync.aligned.m16n8k16.row.col.f32.bf16.bf16.f32 "
        "{%0,%1,%2,%3}, {%4,%5,%6,%7}, {%8,%9}, {%0,%1,%2,%3};"
        : "+f"(d[0]), "+f"(d[1]), "+f"(d[2]), "+f"(d[3])
        : "r"(a[0]), "r"(a[1]), "r"(a[2]), "r"(a[3]), "r"(b0), "r"(b1));
}
__device__ __forceinline__ void mma_f16(float (&d)[4], const uint32_t (&a)[4],
                                        uint32_t b0, uint32_t b1) {
    asm volatile("mma.sync.aligned.m16n8k16.row.col.f32.f16.f16.f32 "
        "{%0,%1,%2,%3}, {%4,%5,%6,%7}, {%8,%9}, {%0,%1,%2,%3};"
        : "+f"(d[0]), "+f"(d[1]), "+f"(d[2]), "+f"(d[3])
        : "r"(a[0]), "r"(a[1]), "r"(a[2]), "r"(a[3]), "r"(b0), "r"(b1));
}
__device__ __forceinline__ void cpasync16(uint32_t saddr, const void* g) {
    asm volatile("cp.async.cg.shared.global [%0], [%1], 16;" :: "r"(saddr), "l"(g));
}
__device__ __forceinline__ void cpasync16z(uint32_t saddr, const void* g, int szbytes) {
    asm volatile("cp.async.cg.shared.global [%0], [%1], 16, %2;"
                 :: "r"(saddr), "l"(g), "r"(szbytes));
}

// ===================== prep =====================
__global__ void k_half(const float* __restrict__ src, __nv_bfloat16* H, __nv_bfloat16* L) {
    int idx = blockIdx.x * blockDim.x + threadIdx.x;
    if (idx >= BT * NP * CC) return;
    int c = idx & 127;
    int t = idx >> 7;
    int n = t & 4095;
    int b = t >> 12;
    int y = n >> 6, x = n & 63;
    float v = src[(((size_t)b*CC + c)*HH + 2*y)*WW + 2*x];
    split_store(H, L, (size_t)idx, v);
}

__global__ void k_ss() {
    int idx = blockIdx.x * blockDim.x + threadIdx.x;
    if (idx >= BT * NP) return;
    const __nv_bfloat162* h2 = (const __nv_bfloat162*)(g_bh + (size_t)idx * CC);
    const __nv_bfloat162* l2 = (const __nv_bfloat162*)(g_bl + (size_t)idx * CC);
    float s = 0.f;
#pragma unroll
    for (int c = 0; c < CC/2; c++) {
        float2 a = __bfloat1622float2(h2[c]);
        float2 bb = __bfloat1622float2(l2[c]);
        float v0 = a.x + bb.x, v1 = a.y + bb.y;
        s += v0*v0 + v1*v1;
    }
    g_ss[idx] = s;
}

__global__ void k_inv() {
    int idx = blockIdx.x * blockDim.x + threadIdx.x;
    if (idx >= BT * NP) return;
    int b = idx >> 12, n = idx & 4095;
    int ny = n >> 6, nx = n & 63;
    float s = 0.f;
#pragma unroll
    for (int i = 0; i < 3; i++)
#pragma unroll
        for (int j = 0; j < 3; j++) {
            int y = ny + i - 1, x = nx + j - 1;
            if ((unsigned)y < 64u && (unsigned)x < 64u)
                s += g_ss[b*NP + y*64 + x];
        }
    g_inv[idx] = 1.f / fmaxf(sqrtf(s), 1e-4f);
}

__global__ void k_bgcl(const float* __restrict__ bg) {
    __shared__ float tile[32][33];
    int b = blockIdx.z;
    int c0 = blockIdx.y * 32;
    int p0 = blockIdx.x * 32;
    int tx = threadIdx.x & 31, ty = threadIdx.x >> 5;
#pragma unroll
    for (int k = 0; k < 4; k++) {
        int c = c0 + ty + k*8;
        tile[ty + k*8][tx] = bg[((size_t)(b*CC + c))*HWF + p0 + tx];
    }
    __syncthreads();
#pragma unroll
    for (int k = 0; k < 4; k++) {
        int p = p0 + ty + k*8;
        g_bgcl[((size_t)(b*HWF + p))*CC + c0 + tx] = __float2half(tile[tx][ty + k*8]);
    }
}

__global__ void k_eq(const float* __restrict__ mask) {
    int n = blockIdx.x * blockDim.x + threadIdx.x;
    if (n >= NP) return;
    int ny = n / HS, nx = n % HS;
    float s = 0.f;
#pragma unroll
    for (int i = 0; i < 3; i++)
#pragma unroll
        for (int j = 0; j < 3; j++) {
            int y = ny + i - 1, x = nx + j - 1;
            if ((unsigned)y < HS && (unsigned)x < HS)
                s += mask[(2*y)*WW + 2*x];
        }
    g_eq[n] = ((s / 9.f) == 0.f) ? 1.f : 0.f;
}

// weight reorder: out[r][tap*128+c] = w[r][c*9+tap], single fp16
__global__ void k_wreorder(const float* __restrict__ w, __half* H) {
    int idx = blockIdx.x * blockDim.x + threadIdx.x;
    if (idx >= CC * K1) return;
    int r = idx / K1;
    int rem = idx % K1;
    int tap = rem >> 7;
    int c = rem & 127;
    H[idx] = __float2half(w[r * K1 + c * 9 + tap]);
}

// ===================== bf16-split GEMM1: 128m x 256n, 3-term ================
#define KT 32
#define STAGES 3
#define M2STAGE (8192*2 + 16384*2)
#define M2SMEM (STAGES*M2STAGE)

__global__ void __launch_bounds__(256, 1) mgemm256(
    const __nv_bfloat16* __restrict__ Ah, const __nv_bfloat16* __restrict__ Al,
    const __nv_bfloat16* __restrict__ Bh, const __nv_bfloat16* __restrict__ Bl,
    float* __restrict__ C, int K, int N,
    size_t sA, size_t sB, size_t sC)
{
    extern __shared__ char sm[];
    const uint32_t smb = smem_u32(sm);
    const int tid = threadIdx.x;
    const int bz = blockIdx.z;
    const int bm = blockIdx.y * 128;
    const int bn = blockIdx.x * 256;
    C += sC * bz;
    const __nv_bfloat16* ah = Ah + sA * bz;
    const __nv_bfloat16* al = Al + sA * bz;
    const __nv_bfloat16* bhp = Bh + sB * bz;
    const __nv_bfloat16* blp = Bl + sB * bz;

    const int NC = K >> 5;

    auto load_stage = [&](int s, int kc) {
#pragma unroll
        for (int it = 0; it < 2; it++) {
            int id = tid + it * 256;
            int row = id >> 2, ch = id & 3;
            uint32_t swz = (uint32_t)(row * 64 + ((ch ^ ((row >> 1) & 3)) << 4));
            cpasync16(smb + s*M2STAGE + swz,        ah + (size_t)(bm + row) * K + kc + ch * 8);
            cpasync16(smb + s*M2STAGE + 8192 + swz, al + (size_t)(bm + row) * K + kc + ch * 8);
        }
#pragma unroll
        for (int it = 0; it < 4; it++) {
            int id = tid + it * 256;
            int row = id >> 2, ch = id & 3;
            uint32_t swz = (uint32_t)(row * 64 + ((ch ^ ((row >> 1) & 3)) << 4));
            cpasync16(smb + s*M2STAGE + 16384 + swz, bhp + (size_t)(bn + row) * K + kc + ch * 8);
            cpasync16(smb + s*M2STAGE + 32768 + swz, blp + (size_t)(bn + row) * K + kc + ch * 8);
        }
        asm volatile("cp.async.commit_group;");
    };

#pragma unroll
    for (int s = 0; s < STAGES - 1; s++) load_stage(s, s * KT);

    const int wid = tid >> 5, lane = tid & 31;
    const int wm = wid & 1, wn = wid >> 1;

    float acc[4][8][4];
#pragma unroll
    for (int a = 0; a < 4; a++)
#pragma unroll
        for (int bb = 0; bb < 8; bb++)
#pragma unroll
            for (int c = 0; c < 4; c++) acc[a][bb][c] = 0.f;

    for (int i = 0; i < NC; i++) {
        asm volatile("cp.async.wait_group 1;");
        __syncthreads();

        if (i + STAGES - 1 < NC)
            load_stage((i + STAGES - 1) % STAGES, (i + STAGES - 1) * KT);
        else
            asm volatile("cp.async.commit_group;");

        const uint32_t stb = smb + (i % STAGES) * M2STAGE;
#pragma unroll
        for (int h = 0; h < 2; h++) {
            uint32_t ar[4][4], alr[4][4];
            uint32_t bh2[8][2], bl2[8][2];
#pragma unroll
            for (int tm = 0; tm < 4; tm++) {
                int row = wm*64 + tm*16 + (lane & 15);
                int ch  = 2*h + (lane >> 4);
                uint32_t ad = stb + row*64 + ((ch ^ ((row >> 1) & 3)) << 4);
                ldsm_x4(ar[tm], ad);
                ldsm_x4(alr[tm], ad + 8192);
            }
#pragma unroll
            for (int tb = 0; tb < 4; tb++) {
                int row = wn*64 + tb*16 + ((lane >> 4) << 3) + (lane & 7);
                int ch  = 2*h + ((lane >> 3) & 1);
                uint32_t bd = stb + 16384 + row*64 + ((ch ^ ((row >> 1) & 3)) << 4);
                uint32_t r[4];
                ldsm_x4(r, bd);
                bh2[tb*2][0] = r[0]; bh2[tb*2][1] = r[1];
                bh2[tb*2+1][0] = r[2]; bh2[tb*2+1][1] = r[3];
                ldsm_x4(r, bd + 16384);
                bl2[tb*2][0] = r[0]; bl2[tb*2][1] = r[1];
                bl2[tb*2+1][0] = r[2]; bl2[tb*2+1][1] = r[3];
            }
#pragma unroll
            for (int tm = 0; tm < 4; tm++)
#pragma unroll
                for (int tn = 0; tn < 8; tn++) {
                    mma_bf16(acc[tm][tn], ar[tm], bh2[tn][0], bh2[tn][1]);
                    mma_bf16(acc[tm][tn], ar[tm], bl2[tn][0], bl2[tn][1]);
                    mma_bf16(acc[tm][tn], alr[tm], bh2[tn][0], bh2[tn][1]);
                }
        }
    }

#pragma unroll
    for (int tm = 0; tm < 4; tm++) {
        int row = bm + wm*64 + tm*16 + (lane >> 2);
#pragma unroll
        for (int hf = 0; hf < 2; hf++) {
            int r = row + hf*8;
            float* dst = C + (size_t)r * N + bn + wn*64 + (lane & 3)*2;
#pragma unroll
            for (int tn = 0; tn < 8; tn++)
                *(float2*)(dst + tn*8) = make_float2(acc[tm][tn][hf*2+0], acc[tm][tn][hf*2+1]);
        }
    }
}

// ===================== implicit conv GEMM: 128ch x 256pix, fp16 1-term W =====
#define CSTAGE (8192 + 16384)
#define CGEMM_SMEM (STAGES*CSTAGE)
#define TPITCH 136

template<int OUT16>
__global__ void __launch_bounds__(256, 1) cgemm(
    const __half* __restrict__ Wh,
    const __half* __restrict__ img,
    float* __restrict__ Cout, __half* __restrict__ out16,
    const float* __restrict__ bias)
{
    extern __shared__ char sm[];
    const uint32_t smb = smem_u32(sm);
    const int tid = threadIdx.x;
    const int bz = blockIdx.z;
    const int bn = blockIdx.x * 256;
    const __half* ib = img + (size_t)bz * HWF * CC;

    const int NC = K1 >> 5;   // 36

    auto load_stage = [&](int s, int kc) {
#pragma unroll
        for (int it = 0; it < 2; it++) {
            int id = tid + it * 256;
            int row = id >> 2, ch = id & 3;
            uint32_t swz = (uint32_t)(row * 64 + ((ch ^ ((row >> 1) & 3)) << 4));
            cpasync16(smb + s*CSTAGE + swz, Wh + (size_t)row * K1 + kc + ch * 8);
        }
        int tap = kc >> 7;
        int ki = tap / 3, kj = tap - ki * 3;
        int c0 = kc & 127;
#pragma unroll
        for (int it = 0; it < 4; it++) {
            int id = tid + it * 256;
            int row = id >> 2, ch = id & 3;
            int p = bn + row;
            int Y = (p >> 7) + ki - 1, X = (p & 127) + kj - 1;
            bool ok = (unsigned)Y < HH && (unsigned)X < WW;
            const __half* g = ok ? ib + ((size_t)(Y * WW + X)) * CC + c0 + ch * 8 : ib;
            uint32_t swz = (uint32_t)(row * 64 + ((ch ^ ((row >> 1) & 3)) << 4));
            cpasync16z(smb + s*CSTAGE + 8192 + swz, g, ok ? 16 : 0);
        }
        asm volatile("cp.async.commit_group;");
    };

#pragma unroll
    for (int s = 0; s < STAGES - 1; s++) load_stage(s, s * KT);

    const int wid = tid >> 5, lane = tid & 31;
    const int wm = wid & 1, wn = wid >> 1;

    float acc[4][8][4];
#pragma unroll
    for (int a = 0; a < 4; a++)
#pragma unroll
        for (int bb = 0; bb < 8; bb++)
#pragma unroll
            for (int c = 0; c < 4; c++) acc[a][bb][c] = 0.f;

    for (int i = 0; i < NC; i++) {
        asm volatile("cp.async.wait_group 1;");
        __syncthreads();

        if (i + STAGES - 1 < NC)
            load_stage((i + STAGES - 1) % STAGES, (i + STAGES - 1) * KT);
        else
            asm volatile("cp.async.commit_group;");

        const uint32_t stb = smb + (i % STAGES) * CSTAGE;
#pragma unroll
        for (int h = 0; h < 2; h++) {
            uint32_t ah[4][4];
            uint32_t bf[8][2];
#pragma unroll
            for (int tm = 0; tm < 4; tm++) {
                int row = wm*64 + tm*16 + (lane & 15);
                int ch  = 2*h + (lane >> 4);
                uint32_t ad = stb + row*64 + ((ch ^ ((row >> 1) & 3)) << 4);
                ldsm_x4(ah[tm], ad);
            }
#pragma unroll
            for (int tb = 0; tb < 4; tb++) {
                int row = wn*64 + tb*16 + ((lane >> 4) << 3) + (lane & 7);
                int ch  = 2*h + ((lane >> 3) & 1);
                uint32_t bd = stb + 8192 + row*64 + ((ch ^ ((row >> 1) & 3)) << 4);
                uint32_t r[4];
                ldsm_x4(r, bd);
                bf[tb*2][0] = r[0]; bf[tb*2][1] = r[1];
                bf[tb*2+1][0] = r[2]; bf[tb*2+1][1] = r[3];
            }
#pragma unroll
            for (int tm = 0; tm < 4; tm++)
#pragma unroll
                for (int tn = 0; tn < 8; tn++)
                    mma_f16(acc[tm][tn], ah[tm], bf[tn][0], bf[tn][1]);
        }
    }

    if (OUT16) {
        asm volatile("cp.async.wait_group 0;");
        __syncthreads();
        __half* st = (__half*)sm;
#pragma unroll
        for (int tm = 0; tm < 4; tm++) {
#pragma unroll
            for (int hf = 0; hf < 2; hf++) {
                int r = wm*64 + tm*16 + (lane >> 2) + hf*8;
                float bv = bias[r];
#pragma unroll
                for (int tn = 0; tn < 8; tn++) {
                    int col = wn*64 + tn*8 + (lane & 3)*2;
                    float x0 = acc[tm][tn][hf*2+0] + bv;
                    float x1 = acc[tm][tn][hf*2+1] + bv;
                    x0 = x0 > 0.f ? x0 : expf(x0) - 1.f;
                    x1 = x1 > 0.f ? x1 : expf(x1) - 1.f;
                    st[(size_t)col * TPITCH + r]       = __float2half(x0);
                    st[(size_t)(col+1) * TPITCH + r]   = __float2half(x1);
                }
            }
        }
        __syncthreads();
        __half* dst = out16 + ((size_t)bz * HWF + bn + tid) * CC;
        const uint4* srcv = (const uint4*)(st + (size_t)tid * TPITCH);
#pragma unroll
        for (int i = 0; i < 16; i++)
            ((uint4*)dst)[i] = srcv[i];
    } else {
        float* C = Cout + (size_t)bz * CC * HWF;
#pragma unroll
        for (int tm = 0; tm < 4; tm++) {
            int row = wm*64 + tm*16 + (lane >> 2);
#pragma unroll
            for (int hf = 0; hf < 2; hf++) {
                int r = row + hf*8;
                float bv = bias[r];
                float* dst = C + (size_t)r * HWF + bn + wn*64 + (lane & 3)*2;
#pragma unroll
                for (int tn = 0; tn < 8; tn++) {
                    float x0 = acc[tm][tn][hf*2+0] + bv;
                    float x1 = acc[tm][tn][hf*2+1] + bv;
                    x0 = x0 > 0.f ? x0 : expf(x0) - 1.f;
                    x1 = x1 > 0.f ? x1 : expf(x1) - 1.f;
                    *(float2*)(dst + tn*8) = make_float2(x0, x1);
                }
            }
        }
    }
}

// ===================== stencil =====================
__global__ void __launch_bounds__(256) k_stencil9(const float* __restrict__ G,
                                                  float* __restrict__ out) {
    __shared__ float t3[3][64][64];
    int bid = blockIdx.x;
    int b = bid >> 12;
    int rest = bid & 4095;
    int ny = rest >> 6, py = rest & 63;
    const float* Gb = G + (size_t)b * NP * NP;
    float* ob = out + (size_t)b * NP * NP;
    int tid = threadIdx.x;

#pragma unroll
    for (int dy = 0; dy < 3; dy++) {
        int gy = ny + dy - 1, gpy = py + dy - 1;
        bool ok = (unsigned)gy < 64 && (unsigned)gpy < 64;
        for (int idx = tid; idx < 4096; idx += 256) {
            int i = idx >> 6, jj = idx & 63;
            t3[dy][i][jj] = ok ? Gb[((size_t)(gy*64 + i)) * NP + gpy*64 + jj] : 0.f;
        }
    }
    __syncthreads();

    int px = tid & 63;
    int nx0 = tid >> 6;
    for (int nx = nx0; nx < 64; nx += 4) {
        float s = 0.f;
#pragma unroll
        for (int dy = 0; dy < 3; dy++)
#pragma unroll
            for (int dx = -1; dx <= 1; dx++) {
                int a = nx + dx, c = px + dx;
                if ((unsigned)a < 64 && (unsigned)c < 64)
                    s += t3[dy][a][c];
            }
        ob[((size_t)(ny*64 + nx)) * NP + py*64 + px] = s * g_inv[b*NP + ny*64 + nx];
    }
}

// ===================== fuse1 + permutation =====================
__global__ void k_fuseperm(const float* __restrict__ in, float* __restrict__ out) {
    __shared__ float tile[64 * 65];
    int brow = blockIdx.x;
    int b = brow / NP, rp = brow % NP;
    int nx = rp >> 6, ny = rp & 63;
    int r = ny * 64 + nx;
    const float* src = in + (size_t)b * NP * NP;
    float*       dst = out + ((size_t)b * NP + rp) * NP;
    int tid = threadIdx.x;
    for (int k = tid; k < NP; k += 256) {
        float f = src[(size_t)r * NP + k];
        if (r > 0 && k > 0)           f += src[(size_t)(r-1) * NP + k - 1];
        if (r < NP-1 && k < NP-1)     f += src[(size_t)(r+1) * NP + k + 1];
        tile[(k & 63) * 65 + (k >> 6)] = f;
    }
    __syncthreads();
    for (int j = tid; j < NP; j += 256)
        dst[j] = tile[(j >> 6) * 65 + (j & 63)];
}

// ===== softmax stats + candidate collection (fuse2 on the fly) ==============
// A selected row must satisfy l > cmax + ln(SEL_THR*csum) >= runningmax - 16.118,
// so recording rows with l > runningmax - CWIN (CWIN=16.2) is a strict superset.
__global__ void k_smax1(const float* __restrict__ in) {
    int col = blockIdx.x * 256 + threadIdx.x;
    int chunk = blockIdx.y;
    int b = blockIdx.z;
    int lane = threadIdx.x & 31;
    const float* base = in + (size_t)b * NP * NP;
    int r0 = chunk * 128;

    float pm1 = (r0 > 0) ? base[(size_t)(r0-1) * NP + col] : 0.f;
    float p0  = base[(size_t)r0 * NP + col];
    float pp1 = (r0 + 1 < NP) ? base[(size_t)(r0+1) * NP + col] : 0.f;

    float mx = -1e30f, sm = 0.f;
    int s = 0;
    size_t slotbase = (((size_t)(b*NP + col)) * 32 + chunk) * SLOTS;
    for (int r = r0; r < r0 + 128; r++) {
        float um1 = __shfl_up_sync(0xffffffffu, pm1, 1);
        if (lane == 0)
            um1 = (r > 0 && col > 0) ? base[(size_t)(r-1) * NP + col - 1] : 0.f;
        float dp1 = __shfl_down_sync(0xffffffffu, pp1, 1);
        if (lane == 31)
            dp1 = (r < NP-1 && col < NP-1) ? base[(size_t)(r+1) * NP + col + 1] : 0.f;
        float v = p0 + um1 + dp1;
        float eqv = g_eq[r];
        float l = v * (eqv * SCALEF);
        if (l > mx) { sm = sm * expf(mx - l) + 1.f; mx = l; }
        else        { sm += expf(l - mx); }
        if (eqv != 0.f && l > mx - CWIN) {
            if (s == SLOTS) {
                // rare: compact, dropping entries now outside the window
                int t = 0;
                for (int i2 = 0; i2 < SLOTS; i2++) {
                    float lv = g_clog[slotbase + i2];
                    if (lv > mx - CWIN) {
                        g_cidx[slotbase + t] = g_cidx[slotbase + i2];
                        g_clog[slotbase + t] = lv;
                        t++;
                    }
                }
                s = t;
            }
            if (s < SLOTS) {
                g_cidx[slotbase + s] = r;
                g_clog[slotbase + s] = l;
                s++;
            }
        }
        pm1 = p0; p0 = pp1;
        pp1 = (r + 2 < NP) ? base[(size_t)(r+2) * NP + col] : 0.f;
    }
    g_pmax[((size_t)b * 32 + chunk) * NP + col] = mx;
    g_psum[((size_t)b * 32 + chunk) * NP + col] = sm;
    g_ccnt[(b*NP + col) * 32 + chunk] = s;
}

__global__ void k_smax2() {
    int idx = blockIdx.x * blockDim.x + threadIdx.x;
    if (idx >= BT * NP) return;
    int b = idx / NP, col = idx % NP;
    float M = -1e30f;
    for (int i = 0; i < 32; i++)
        M = fmaxf(M, g_pmax[((size_t)b * 32 + i) * NP + col]);
    float S = 0.f;
    for (int i = 0; i < 32; i++)
        S += g_psum[((size_t)b * 32 + i) * NP + col] *
             expf(g_pmax[((size_t)b * 32 + i) * NP + col] - M);
    g_cmax[idx] = M;
    g_csum[idx] = S;
    g_lthr[idx] = M + logf(SEL_THR * S);
}

// ===================== candidate filter + merge ==============================
__global__ void k_filter() {
    int idx = blockIdx.x * blockDim.x + threadIdx.x;
    if (idx >= BT * NP) return;
    float lth = g_lthr[idx];
    float M   = g_cmax[idx];
    float Sin = 1.f / g_csum[idx];
    int cnt = 0;
    size_t ob = (size_t)idx * KMAX;
    for (int ch = 0; ch < 32; ch++) {
        int c = g_ccnt[idx * 32 + ch];
        size_t sb = (((size_t)idx) * 32 + ch) * SLOTS;
        for (int i = 0; i < c; i++) {
            float l = g_clog[sb + i];
            if (l > lth && cnt < KMAX) {
                int r = g_cidx[sb + i];
                g_midx[ob + cnt] = r;
                g_mwgt[ob + cnt] = expf(l - M) * Sin * g_eq[r];
                cnt++;
            }
        }
    }
    g_mcnt[idx] = cnt;
}

// ===================== sparse apply + transposed-conv gather ================
__global__ void k_apply() {
    int wid = threadIdx.x >> 5, lane = threadIdx.x & 31;
    int P = blockIdx.x * 8 + wid;
    int b = blockIdx.y;
    int Y = P >> 7, X = P & 127;
    const __half* bgc = g_bgcl + (size_t)b * HWF * CC;
    float4 acc = make_float4(0.f, 0.f, 0.f, 0.f);
#pragma unroll
    for (int di = 0; di < 4; di++) {
        int ty = Y + 1 - di;
        if (ty < 0 || (ty & 1)) continue;
        int my = ty >> 1;
        if (my >= HS) continue;
#pragma unroll
        for (int dj = 0; dj < 4; dj++) {
            int tx = X + 1 - dj;
            if (tx < 0 || (tx & 1)) continue;
            int mx = tx >> 1;
            if (mx >= HS) continue;
            int p = my * 64 + mx;
            int lb = b * NP + p;
            int cnt = g_mcnt[lb];
            const int*   il = g_midx + (size_t)lb * KMAX;
            const float* wl = g_mwgt + (size_t)lb * KMAX;
            for (int i = 0; i < cnt; i++) {
                int m = il[i];
                float w = wl[i];
                int miy = m >> 6, mix = m & 63;
                int Ys = 2*miy + di - 1, Xs = 2*mix + dj - 1;
                if ((unsigned)Ys >= HH || (unsigned)Xs >= WW) continue;
                union { uint2 u; __half2 h[2]; } v;
                v.u = *(const uint2*)(bgc + ((size_t)(Ys * WW + Xs)) * CC + lane * 4);
                float2 a0 = __half22float2(v.h[0]);
                float2 a1 = __half22float2(v.h[1]);
                acc.x += w * a0.x; acc.y += w * a0.y;
                acc.z += w * a1.x; acc.w += w * a1.y;
            }
        }
    }
    union { __half2 h[2]; uint2 u; } cv;
    cv.h[0] = __floats2half2_rn(acc.x * 0.25f, acc.y * 0.25f);
    cv.h[1] = __floats2half2_rn(acc.z * 0.25f, acc.w * 0.25f);
    *(uint2*)(g_y16 + ((size_t)b * HWF + P) * CC + lane * 4) = cv.u;
}

// ===================== host orchestration =====================
extern "C" void kernel_launch(void* const* d_in, const int* in_sizes, int n_in,
                              void* d_out, int out_size) {
    const float* fg   = (const float*)d_in[0];
    const float* bg   = (const float*)d_in[1];
    const float* mask = (const float*)d_in[2];
    const float* w1   = (const float*)d_in[3];
    const float* b1   = (const float*)d_in[4];
    const float* w2   = (const float*)d_in[5];
    const float* b2   = (const float*)d_in[6];
    float* out = (float*)d_out;

    cudaFuncSetAttribute(mgemm256, cudaFuncAttributeMaxDynamicSharedMemorySize, M2SMEM);
    cudaFuncSetAttribute(cgemm<0>, cudaFuncAttributeMaxDynamicSharedMemorySize, CGEMM_SMEM);
    cudaFuncSetAttribute(cgemm<1>, cudaFuncAttributeMaxDynamicSharedMemorySize, CGEMM_SMEM);

    __nv_bfloat16 *bh, *bl, *fh, *fl;
    __half *y16, *h16, *w116, *w216;
    float *bufA, *bufB;
    cudaGetSymbolAddress((void**)&bh, g_bh);     cudaGetSymbolAddress((void**)&bl, g_bl);
    cudaGetSymbolAddress((void**)&fh, g_fh);     cudaGetSymbolAddress((void**)&fl, g_fl);
    cudaGetSymbolAddress((void**)&y16, g_y16);   cudaGetSymbolAddress((void**)&h16, g_h16);
    cudaGetSymbolAddress((void**)&w116, g_w116); cudaGetSymbolAddress((void**)&w216, g_w216);
    cudaGetSymbolAddress((void**)&bufA, g_bufA);
    cudaGetSymbolAddress((void**)&bufB, g_bufB);

    // prep
    k_half    <<<(BT*NP*CC + 255)/256, 256>>>(bg, bh, bl);
    k_half    <<<(BT*NP*CC + 255)/256, 256>>>(fg, fh, fl);
    k_ss      <<<(BT*NP + 255)/256, 256>>>();
    k_inv     <<<(BT*NP + 255)/256, 256>>>();
    k_bgcl    <<<dim3(HWF/32, CC/32, BT), 256>>>(bg);
    k_eq      <<<16, 256>>>(mask);
    k_wreorder<<<(CC*K1 + 255)/256, 256>>>(w1, w116);
    k_wreorder<<<(CC*K1 + 255)/256, 256>>>(w2, w216);

    // GEMM1: G[u][v] = sum_c b[u][c] f[v][c]  (bf16 3-term, 128x256) -> bufA
    mgemm256<<<dim3(16, 32, BT), 256, M2SMEM>>>(
        bh, bl, fh, fl, bufA, CC, NP,
        (size_t)NP * CC, (size_t)NP * CC, (size_t)NP * NP);

    // scores = 9-tap diagonal stencil / norm -> bufB
    k_stencil9<<<BT * 4096, 256>>>(bufA, bufB);

    // fuse1 + permutation -> bufA
    k_fuseperm<<<BT * NP, 256>>>(bufB, bufA);

    // fuse2 on-the-fly + softmax stats + candidate collection
    k_smax1<<<dim3(16, 32, BT), 256>>>(bufA);
    k_smax2<<<32, 256>>>();

    // filter candidates -> merged survivor lists
    k_filter<<<32, 256>>>();

    // sparse attention apply + transposed-conv gather -> y16
    k_apply<<<dim3(HWF/8, BT), 256>>>();

    // conv1 + ELU (implicit, fp16 1-term W) -> h16 image
    cgemm<1><<<dim3(HWF/256, 1, BT), 256, CGEMM_SMEM>>>(
        w116, y16, nullptr, h16, b1);

    // conv2 + ELU (implicit) -> out fp32 NCHW
    cgemm<0><<<dim3(HWF/256, 1, BT), 256, CGEMM_SMEM>>>(
        w216, h16, out, nullptr, b2);
}

// round 16
// speedup vs baseline: 1.0129x; 1.0129x over previous
#include <cuda_runtime.h>
#include <cuda_bf16.h>
#include <cuda_fp16.h>
#include <math.h>
#include <stdint.h>

#define BT 2
#define CC 128
#define HH 128
#define WW 128
#define HS 64
#define NP 4096
#define K1 1152
#define HWF 16384
#define SCALEF 10.0f
#define SEL_THR 1e-7f
#define SLOTS 16
#define KMAX 128

// ===================== scratch =====================
__device__ __align__(256) __nv_bfloat16 g_bh [(size_t)BT*NP*CC];
__device__ __align__(256) __nv_bfloat16 g_bl [(size_t)BT*NP*CC];
__device__ __align__(256) __nv_bfloat16 g_fh [(size_t)BT*NP*CC];
__device__ __align__(256) __nv_bfloat16 g_fl [(size_t)BT*NP*CC];
__device__ __align__(256) __half        g_bgcl[(size_t)BT*HWF*CC]; // bg channels-last fp16
__device__ __align__(256) __half        g_y16 [(size_t)BT*HWF*CC]; // y image channels-last
__device__ __align__(256) __half        g_h16 [(size_t)BT*HWF*CC]; // h image channels-last
__device__ __align__(256) __half        g_w116[CC*K1];
__device__ __align__(256) __half        g_w216[CC*K1];
__device__ __align__(256) float g_bufA[(size_t)BT*NP*NP];
__device__ __align__(256) float g_bufB[(size_t)BT*NP*NP];
__device__ int   g_cidx[(size_t)BT*NP*32*SLOTS];
__device__ float g_cwgt[(size_t)BT*NP*32*SLOTS];
__device__ int   g_ccnt[BT*NP*32];
__device__ int   g_midx[(size_t)BT*NP*KMAX];
__device__ float g_mwgt[(size_t)BT*NP*KMAX];
__device__ int   g_mcnt[BT*NP];
__device__ float g_eq  [NP];
__device__ float g_ss  [BT*NP];
__device__ float g_inv [BT*NP];
__device__ float g_pmax[BT*32*NP];
__device__ float g_psum[BT*32*NP];
__device__ float g_cmax[BT*NP];
__device__ float g_csum[BT*NP];
__device__ float g_lthr[BT*NP];

__device__ __forceinline__ void split_store(__nv_bfloat16* H, __nv_bfloat16* L,
                                            size_t idx, float v) {
    __nv_bfloat16 h = __float2bfloat16(v);
    H[idx] = h;
    L[idx] = __float2bfloat16(v - __bfloat162float(h));
}
__device__ __forceinline__ uint32_t smem_u32(const void* p) {
    uint32_t a;
    asm("{ .reg .u64 t; cvta.to.shared.u64 t, %1; cvt.u32.u64 %0, t; }" : "=r"(a) : "l"(p));
    return a;
}
__device__ __forceinline__ void ldsm_x4(uint32_t (&r)[4], uint32_t addr) {
    asm volatile("ldmatrix.sync.aligned.m8n8.x4.shared.b16 {%0,%1,%2,%3}, [%4];"
                 : "=r"(r[0]), "=r"(r[1]), "=r"(r[2]), "=r"(r[3]) : "r"(addr));
}
__device__ __forceinline__ void mma_bf16(float (&d)[4], const uint32_t (&a)[4],
                                         uint32_t b0, uint32_t b1) {
    asm volatile("mma.sync.aligned.m16n8k16.row.col.f32.bf16.bf16.f32 "
        "{%0,%1,%2,%3}, {%4,%5,%6,%7}, {%8,%9}, {%0,%1,%2,%3};"
        : "+f"(d[0]), "+f"(d[1]), "+f"(d[2]), "+f"(d[3])
        : "r"(a[0]), "r"(a[1]), "r"(a[2]), "r"(a[3]), "r"(b0), "r"(b1));
}
__device__ __forceinline__ void mma_f16(float (&d)[4], const uint32_t (&a)[4],
                                        uint32_t b0, uint32_t b1) {
    asm volatile("mma.sync.aligned.m16n8k16.row.col.f32.f16.f16.f32 "
        "{%0,%1,%2,%3}, {%4,%5,%6,%7}, {%8,%9}, {%0,%1,%2,%3};"
        : "+f"(d[0]), "+f"(d[1]), "+f"(d[2]), "+f"(d[3])
        : "r"(a[0]), "r"(a[1]), "r"(a[2]), "r"(a[3]), "r"(b0), "r"(b1));
}
__device__ __forceinline__ void cpasync16(uint32_t saddr, const void* g) {
    asm volatile("cp.async.cg.shared.global [%0], [%1], 16;" :: "r"(saddr), "l"(g));
}
__device__ __forceinline__ void cpasync16z(uint32_t saddr, const void* g, int szbytes) {
    asm volatile("cp.async.cg.shared.global [%0], [%1], 16, %2;"
                 :: "r"(saddr), "l"(g), "r"(szbytes));
}

// ===================== prep =====================
__global__ void k_half(const float* __restrict__ src, __nv_bfloat16* H, __nv_bfloat16* L) {
    int idx = blockIdx.x * blockDim.x + threadIdx.x;
    if (idx >= BT * NP * CC) return;
    int c = idx & 127;
    int t = idx >> 7;
    int n = t & 4095;
    int b = t >> 12;
    int y = n >> 6, x = n & 63;
    float v = src[(((size_t)b*CC + c)*HH + 2*y)*WW + 2*x];
    split_store(H, L, (size_t)idx, v);
}

__global__ void k_ss() {
    int idx = blockIdx.x * blockDim.x + threadIdx.x;
    if (idx >= BT * NP) return;
    const __nv_bfloat162* h2 = (const __nv_bfloat162*)(g_bh + (size_t)idx * CC);
    const __nv_bfloat162* l2 = (const __nv_bfloat162*)(g_bl + (size_t)idx * CC);
    float s = 0.f;
#pragma unroll
    for (int c = 0; c < CC/2; c++) {
        float2 a = __bfloat1622float2(h2[c]);
        float2 bb = __bfloat1622float2(l2[c]);
        float v0 = a.x + bb.x, v1 = a.y + bb.y;
        s += v0*v0 + v1*v1;
    }
    g_ss[idx] = s;
}

__global__ void k_inv() {
    int idx = blockIdx.x * blockDim.x + threadIdx.x;
    if (idx >= BT * NP) return;
    int b = idx >> 12, n = idx & 4095;
    int ny = n >> 6, nx = n & 63;
    float s = 0.f;
#pragma unroll
    for (int i = 0; i < 3; i++)
#pragma unroll
        for (int j = 0; j < 3; j++) {
            int y = ny + i - 1, x = nx + j - 1;
            if ((unsigned)y < 64u && (unsigned)x < 64u)
                s += g_ss[b*NP + y*64 + x];
        }
    g_inv[idx] = 1.f / fmaxf(sqrtf(s), 1e-4f);
}

__global__ void k_bgcl(const float* __restrict__ bg) {
    __shared__ float tile[32][33];
    int b = blockIdx.z;
    int c0 = blockIdx.y * 32;
    int p0 = blockIdx.x * 32;
    int tx = threadIdx.x & 31, ty = threadIdx.x >> 5;
#pragma unroll
    for (int k = 0; k < 4; k++) {
        int c = c0 + ty + k*8;
        tile[ty + k*8][tx] = bg[((size_t)(b*CC + c))*HWF + p0 + tx];
    }
    __syncthreads();
#pragma unroll
    for (int k = 0; k < 4; k++) {
        int p = p0 + ty + k*8;
        g_bgcl[((size_t)(b*HWF + p))*CC + c0 + tx] = __float2half(tile[tx][ty + k*8]);
    }
}

__global__ void k_eq(const float* __restrict__ mask) {
    int n = blockIdx.x * blockDim.x + threadIdx.x;
    if (n >= NP) return;
    int ny = n / HS, nx = n % HS;
    float s = 0.f;
#pragma unroll
    for (int i = 0; i < 3; i++)
#pragma unroll
        for (int j = 0; j < 3; j++) {
            int y = ny + i - 1, x = nx + j - 1;
            if ((unsigned)y < HS && (unsigned)x < HS)
                s += mask[(2*y)*WW + 2*x];
        }
    g_eq[n] = ((s / 9.f) == 0.f) ? 1.f : 0.f;
}

// weight reorder: out[r][tap*128+c] = w[r][c*9+tap], single fp16
__global__ void k_wreorder(const float* __restrict__ w, __half* H) {
    int idx = blockIdx.x * blockDim.x + threadIdx.x;
    if (idx >= CC * K1) return;
    int r = idx / K1;
    int rem = idx % K1;
    int tap = rem >> 7;
    int c = rem & 127;
    H[idx] = __float2half(w[r * K1 + c * 9 + tap]);
}

// ===================== bf16-split GEMM1: 128m x 256n, 3-term ================
#define KT 32
#define STAGES 3
#define M2STAGE (8192*2 + 16384*2)
#define M2SMEM (STAGES*M2STAGE)

__global__ void __launch_bounds__(256, 1) mgemm256(
    const __nv_bfloat16* __restrict__ Ah, const __nv_bfloat16* __restrict__ Al,
    const __nv_bfloat16* __restrict__ Bh, const __nv_bfloat16* __restrict__ Bl,
    float* __restrict__ C, int K, int N,
    size_t sA, size_t sB, size_t sC)
{
    extern __shared__ char sm[];
    const uint32_t smb = smem_u32(sm);
    const int tid = threadIdx.x;
    const int bz = blockIdx.z;
    const int bm = blockIdx.y * 128;
    const int bn = blockIdx.x * 256;
    C += sC * bz;
    const __nv_bfloat16* ah = Ah + sA * bz;
    const __nv_bfloat16* al = Al + sA * bz;
    const __nv_bfloat16* bhp = Bh + sB * bz;
    const __nv_bfloat16* blp = Bl + sB * bz;

    const int NC = K >> 5;

    auto load_stage = [&](int s, int kc) {
#pragma unroll
        for (int it = 0; it < 2; it++) {
            int id = tid + it * 256;
            int row = id >> 2, ch = id & 3;
            uint32_t swz = (uint32_t)(row * 64 + ((ch ^ ((row >> 1) & 3)) << 4));
            cpasync16(smb + s*M2STAGE + swz,        ah + (size_t)(bm + row) * K + kc + ch * 8);
            cpasync16(smb + s*M2STAGE + 8192 + swz, al + (size_t)(bm + row) * K + kc + ch * 8);
        }
#pragma unroll
        for (int it = 0; it < 4; it++) {
            int id = tid + it * 256;
            int row = id >> 2, ch = id & 3;
            uint32_t swz = (uint32_t)(row * 64 + ((ch ^ ((row >> 1) & 3)) << 4));
            cpasync16(smb + s*M2STAGE + 16384 + swz, bhp + (size_t)(bn + row) * K + kc + ch * 8);
            cpasync16(smb + s*M2STAGE + 32768 + swz, blp + (size_t)(bn + row) * K + kc + ch * 8);
        }
        asm volatile("cp.async.commit_group;");
    };

#pragma unroll
    for (int s = 0; s < STAGES - 1; s++) load_stage(s, s * KT);

    const int wid = tid >> 5, lane = tid & 31;
    const int wm = wid & 1, wn = wid >> 1;

    float acc[4][8][4];
#pragma unroll
    for (int a = 0; a < 4; a++)
#pragma unroll
        for (int bb = 0; bb < 8; bb++)
#pragma unroll
            for (int c = 0; c < 4; c++) acc[a][bb][c] = 0.f;

    for (int i = 0; i < NC; i++) {
        asm volatile("cp.async.wait_group 1;");
        __syncthreads();

        if (i + STAGES - 1 < NC)
            load_stage((i + STAGES - 1) % STAGES, (i + STAGES - 1) * KT);
        else
            asm volatile("cp.async.commit_group;");

        const uint32_t stb = smb + (i % STAGES) * M2STAGE;
#pragma unroll
        for (int h = 0; h < 2; h++) {
            uint32_t ar[4][4], alr[4][4];
            uint32_t bh2[8][2], bl2[8][2];
#pragma unroll
            for (int tm = 0; tm < 4; tm++) {
                int row = wm*64 + tm*16 + (lane & 15);
                int ch  = 2*h + (lane >> 4);
                uint32_t ad = stb + row*64 + ((ch ^ ((row >> 1) & 3)) << 4);
                ldsm_x4(ar[tm], ad);
                ldsm_x4(alr[tm], ad + 8192);
            }
#pragma unroll
            for (int tb = 0; tb < 4; tb++) {
                int row = wn*64 + tb*16 + ((lane >> 4) << 3) + (lane & 7);
                int ch  = 2*h + ((lane >> 3) & 1);
                uint32_t bd = stb + 16384 + row*64 + ((ch ^ ((row >> 1) & 3)) << 4);
                uint32_t r[4];
                ldsm_x4(r, bd);
                bh2[tb*2][0] = r[0]; bh2[tb*2][1] = r[1];
                bh2[tb*2+1][0] = r[2]; bh2[tb*2+1][1] = r[3];
                ldsm_x4(r, bd + 16384);
                bl2[tb*2][0] = r[0]; bl2[tb*2][1] = r[1];
                bl2[tb*2+1][0] = r[2]; bl2[tb*2+1][1] = r[3];
            }
#pragma unroll
            for (int tm = 0; tm < 4; tm++)
#pragma unroll
                for (int tn = 0; tn < 8; tn++) {
                    mma_bf16(acc[tm][tn], ar[tm], bh2[tn][0], bh2[tn][1]);
                    mma_bf16(acc[tm][tn], ar[tm], bl2[tn][0], bl2[tn][1]);
                    mma_bf16(acc[tm][tn], alr[tm], bh2[tn][0], bh2[tn][1]);
                }
        }
    }

#pragma unroll
    for (int tm = 0; tm < 4; tm++) {
        int row = bm + wm*64 + tm*16 + (lane >> 2);
#pragma unroll
        for (int hf = 0; hf < 2; hf++) {
            int r = row + hf*8;
            float* dst = C + (size_t)r * N + bn + wn*64 + (lane & 3)*2;
#pragma unroll
            for (int tn = 0; tn < 8; tn++)
                *(float2*)(dst + tn*8) = make_float2(acc[tm][tn][hf*2+0], acc[tm][tn][hf*2+1]);
        }
    }
}

// ===================== implicit conv GEMM: 128ch x 256pix, fp16 1-term W =====
#define CSTAGE (8192 + 16384)
#define CGEMM_SMEM (STAGES*CSTAGE)
#define TPITCH 136

template<int OUT16>
__global__ void __launch_bounds__(256, 1) cgemm(
    const __half* __restrict__ Wh,
    const __half* __restrict__ img,
    float* __restrict__ Cout, __half* __restrict__ out16,
    const float* __restrict__ bias)
{
    extern __shared__ char sm[];
    const uint32_t smb = smem_u32(sm);
    const int tid = threadIdx.x;
    const int bz = blockIdx.z;
    const int bn = blockIdx.x * 256;
    const __half* ib = img + (size_t)bz * HWF * CC;

    const int NC = K1 >> 5;   // 36

    auto load_stage = [&](int s, int kc) {
#pragma unroll
        for (int it = 0; it < 2; it++) {
            int id = tid + it * 256;
            int row = id >> 2, ch = id & 3;
            uint32_t swz = (uint32_t)(row * 64 + ((ch ^ ((row >> 1) & 3)) << 4));
            cpasync16(smb + s*CSTAGE + swz, Wh + (size_t)row * K1 + kc + ch * 8);
        }
        int tap = kc >> 7;
        int ki = tap / 3, kj = tap - ki * 3;
        int c0 = kc & 127;
#pragma unroll
        for (int it = 0; it < 4; it++) {
            int id = tid + it * 256;
            int row = id >> 2, ch = id & 3;
            int p = bn + row;
            int Y = (p >> 7) + ki - 1, X = (p & 127) + kj - 1;
            bool ok = (unsigned)Y < HH && (unsigned)X < WW;
            const __half* g = ok ? ib + ((size_t)(Y * WW + X)) * CC + c0 + ch * 8 : ib;
            uint32_t swz = (uint32_t)(row * 64 + ((ch ^ ((row >> 1) & 3)) << 4));
            cpasync16z(smb + s*CSTAGE + 8192 + swz, g, ok ? 16 : 0);
        }
        asm volatile("cp.async.commit_group;");
    };

#pragma unroll
    for (int s = 0; s < STAGES - 1; s++) load_stage(s, s * KT);

    const int wid = tid >> 5, lane = tid & 31;
    const int wm = wid & 1, wn = wid >> 1;

    float acc[4][8][4];
#pragma unroll
    for (int a = 0; a < 4; a++)
#pragma unroll
        for (int bb = 0; bb < 8; bb++)
#pragma unroll
            for (int c = 0; c < 4; c++) acc[a][bb][c] = 0.f;

    for (int i = 0; i < NC; i++) {
        asm volatile("cp.async.wait_group 1;");
        __syncthreads();

        if (i + STAGES - 1 < NC)
            load_stage((i + STAGES - 1) % STAGES, (i + STAGES - 1) * KT);
        else
            asm volatile("cp.async.commit_group;");

        const uint32_t stb = smb + (i % STAGES) * CSTAGE;
#pragma unroll
        for (int h = 0; h < 2; h++) {
            uint32_t ah[4][4];
            uint32_t bf[8][2];
#pragma unroll
            for (int tm = 0; tm < 4; tm++) {
                int row = wm*64 + tm*16 + (lane & 15);
                int ch  = 2*h + (lane >> 4);
                uint32_t ad = stb + row*64 + ((ch ^ ((row >> 1) & 3)) << 4);
                ldsm_x4(ah[tm], ad);
            }
#pragma unroll
            for (int tb = 0; tb < 4; tb++) {
                int row = wn*64 + tb*16 + ((lane >> 4) << 3) + (lane & 7);
                int ch  = 2*h + ((lane >> 3) & 1);
                uint32_t bd = stb + 8192 + row*64 + ((ch ^ ((row >> 1) & 3)) << 4);
                uint32_t r[4];
                ldsm_x4(r, bd);
                bf[tb*2][0] = r[0]; bf[tb*2][1] = r[1];
                bf[tb*2+1][0] = r[2]; bf[tb*2+1][1] = r[3];
            }
#pragma unroll
            for (int tm = 0; tm < 4; tm++)
#pragma unroll
                for (int tn = 0; tn < 8; tn++)
                    mma_f16(acc[tm][tn], ah[tm], bf[tn][0], bf[tn][1]);
        }
    }

    if (OUT16) {
        asm volatile("cp.async.wait_group 0;");
        __syncthreads();
        __half* st = (__half*)sm;
#pragma unroll
        for (int tm = 0; tm < 4; tm++) {
#pragma unroll
            for (int hf = 0; hf < 2; hf++) {
                int r = wm*64 + tm*16 + (lane >> 2) + hf*8;
                float bv = bias[r];
#pragma unroll
                for (int tn = 0; tn < 8; tn++) {
                    int col = wn*64 + tn*8 + (lane & 3)*2;
                    float x0 = acc[tm][tn][hf*2+0] + bv;
                    float x1 = acc[tm][tn][hf*2+1] + bv;
                    x0 = x0 > 0.f ? x0 : expf(x0) - 1.f;
                    x1 = x1 > 0.f ? x1 : expf(x1) - 1.f;
                    st[(size_t)col * TPITCH + r]       = __float2half(x0);
                    st[(size_t)(col+1) * TPITCH + r]   = __float2half(x1);
                }
            }
        }
        __syncthreads();
        __half* dst = out16 + ((size_t)bz * HWF + bn + tid) * CC;
        const uint4* srcv = (const uint4*)(st + (size_t)tid * TPITCH);
#pragma unroll
        for (int i = 0; i < 16; i++)
            ((uint4*)dst)[i] = srcv[i];
    } else {
        float* C = Cout + (size_t)bz * CC * HWF;
#pragma unroll
        for (int tm = 0; tm < 4; tm++) {
            int row = wm*64 + tm*16 + (lane >> 2);
#pragma unroll
            for (int hf = 0; hf < 2; hf++) {
                int r = row + hf*8;
                float bv = bias[r];
                float* dst = C + (size_t)r * HWF + bn + wn*64 + (lane & 3)*2;
#pragma unroll
                for (int tn = 0; tn < 8; tn++) {
                    float x0 = acc[tm][tn][hf*2+0] + bv;
                    float x1 = acc[tm][tn][hf*2+1] + bv;
                    x0 = x0 > 0.f ? x0 : expf(x0) - 1.f;
                    x1 = x1 > 0.f ? x1 : expf(x1) - 1.f;
                    *(float2*)(dst + tn*8) = make_float2(x0, x1);
                }
            }
        }
    }
}

// ===================== stencil =====================
__global__ void __launch_bounds__(256) k_stencil9(const float* __restrict__ G,
                                                  float* __restrict__ out) {
    __shared__ float t3[3][64][64];
    int bid = blockIdx.x;
    int b = bid >> 12;
    int rest = bid & 4095;
    int ny = rest >> 6, py = rest & 63;
    const float* Gb = G + (size_t)b * NP * NP;
    float* ob = out + (size_t)b * NP * NP;
    int tid = threadIdx.x;

#pragma unroll
    for (int dy = 0; dy < 3; dy++) {
        int gy = ny + dy - 1, gpy = py + dy - 1;
        bool ok = (unsigned)gy < 64 && (unsigned)gpy < 64;
        for (int idx = tid; idx < 4096; idx += 256) {
            int i = idx >> 6, jj = idx & 63;
            t3[dy][i][jj] = ok ? Gb[((size_t)(gy*64 + i)) * NP + gpy*64 + jj] : 0.f;
        }
    }
    __syncthreads();

    int px = tid & 63;
    int nx0 = tid >> 6;
    for (int nx = nx0; nx < 64; nx += 4) {
        float s = 0.f;
#pragma unroll
        for (int dy = 0; dy < 3; dy++)
#pragma unroll
            for (int dx = -1; dx <= 1; dx++) {
                int a = nx + dx, c = px + dx;
                if ((unsigned)a < 64 && (unsigned)c < 64)
                    s += t3[dy][a][c];
            }
        ob[((size_t)(ny*64 + nx)) * NP + py*64 + px] = s * g_inv[b*NP + ny*64 + nx];
    }
}

// ===================== fuse1 + permutation =====================
__global__ void k_fuseperm(const float* __restrict__ in, float* __restrict__ out) {
    __shared__ float tile[64 * 65];
    int brow = blockIdx.x;
    int b = brow / NP, rp = brow % NP;
    int nx = rp >> 6, ny = rp & 63;
    int r = ny * 64 + nx;
    const float* src = in + (size_t)b * NP * NP;
    float*       dst = out + ((size_t)b * NP + rp) * NP;
    int tid = threadIdx.x;
    for (int k = tid; k < NP; k += 256) {
        float f = src[(size_t)r * NP + k];
        if (r > 0 && k > 0)           f += src[(size_t)(r-1) * NP + k - 1];
        if (r < NP-1 && k < NP-1)     f += src[(size_t)(r+1) * NP + k + 1];
        tile[(k & 63) * 65 + (k >> 6)] = f;
    }
    __syncthreads();
    for (int j = tid; j < NP; j += 256)
        dst[j] = tile[(j >> 6) * 65 + (j & 63)];
}

// ===================== softmax stats (fuse2 on the fly, 2 cols/thread) =======
__global__ void k_smax1(const float* __restrict__ in) {
    int t = threadIdx.x;
    int c0 = blockIdx.x * 512 + t * 2;     // this thread: cols c0, c0+1
    int chunk = blockIdx.y;
    int b = blockIdx.z;
    int lane = t & 31;
    const float* base = in + (size_t)b * NP * NP;
    int r0 = chunk * 128;

    float2 pm1 = (r0 > 0) ? *(const float2*)(base + (size_t)(r0-1) * NP + c0)
                          : make_float2(0.f, 0.f);
    float2 p0  = *(const float2*)(base + (size_t)r0 * NP + c0);
    float2 pp1 = (r0 + 1 < NP) ? *(const float2*)(base + (size_t)(r0+1) * NP + c0)
                               : make_float2(0.f, 0.f);

    float mx0 = -1e30f, sm0 = 0.f, mx1 = -1e30f, sm1 = 0.f;
    for (int r = r0; r < r0 + 128; r++) {
        // col c0: um1 = base[r-1][c0-1] (prev thread's pm1.y); dp1 = pp1.y
        float um0 = __shfl_up_sync(0xffffffffu, pm1.y, 1);
        if (lane == 0)
            um0 = (r > 0 && c0 > 0) ? base[(size_t)(r-1) * NP + c0 - 1] : 0.f;
        float dp0 = (r < NP-1) ? pp1.y : 0.f;
        // col c0+1: um1 = pm1.x; dp1 = base[r+1][c0+2] (next thread's pp1.x)
        float um1v = (r > 0) ? pm1.x : 0.f;
        float dp1v = __shfl_down_sync(0xffffffffu, pp1.x, 1);
        if (lane == 31)
            dp1v = (r < NP-1 && c0 + 2 < NP) ? base[(size_t)(r+1) * NP + c0 + 2] : 0.f;

        float eqs = g_eq[r] * SCALEF;
        float l0 = (p0.x + um0 + dp0) * eqs;
        float l1 = (p0.y + um1v + dp1v) * eqs;
        if (l0 > mx0) { sm0 = sm0 * expf(mx0 - l0) + 1.f; mx0 = l0; }
        else          { sm0 += expf(l0 - mx0); }
        if (l1 > mx1) { sm1 = sm1 * expf(mx1 - l1) + 1.f; mx1 = l1; }
        else          { sm1 += expf(l1 - mx1); }

        pm1 = p0; p0 = pp1;
        pp1 = (r + 2 < NP) ? *(const float2*)(base + (size_t)(r+2) * NP + c0)
                           : make_float2(0.f, 0.f);
    }
    size_t sb = ((size_t)b * 32 + chunk) * NP + c0;
    g_pmax[sb]     = mx0;  g_pmax[sb + 1] = mx1;
    g_psum[sb]     = sm0;  g_psum[sb + 1] = sm1;
}

__global__ void k_smax2() {
    int idx = blockIdx.x * blockDim.x + threadIdx.x;
    if (idx >= BT * NP) return;
    int b = idx / NP, col = idx % NP;
    float M = -1e30f;
    for (int i = 0; i < 32; i++)
        M = fmaxf(M, g_pmax[((size_t)b * 32 + i) * NP + col]);
    float S = 0.f;
    for (int i = 0; i < 32; i++)
        S += g_psum[((size_t)b * 32 + i) * NP + col] *
             expf(g_pmax[((size_t)b * 32 + i) * NP + col] - M);
    g_cmax[idx] = M;
    g_csum[idx] = S;
    g_lthr[idx] = M + logf(SEL_THR * S);
}

// ===================== sparse selection (2 cols/thread) ======================
__global__ void k_sel(const float* __restrict__ in) {
    int t = threadIdx.x;
    int c0 = blockIdx.x * 512 + t * 2;
    int chunk = blockIdx.y;
    int b = blockIdx.z;
    int lane = t & 31;
    const float* base = in + (size_t)b * NP * NP;
    int r0 = chunk * 128;

    float lth0 = g_lthr[b*NP + c0],     lth1 = g_lthr[b*NP + c0 + 1];
    float M0   = g_cmax[b*NP + c0],     M1   = g_cmax[b*NP + c0 + 1];
    float Si0  = 1.f / g_csum[b*NP + c0], Si1 = 1.f / g_csum[b*NP + c0 + 1];

    float2 pm1 = (r0 > 0) ? *(const float2*)(base + (size_t)(r0-1) * NP + c0)
                          : make_float2(0.f, 0.f);
    float2 p0  = *(const float2*)(base + (size_t)r0 * NP + c0);
    float2 pp1 = (r0 + 1 < NP) ? *(const float2*)(base + (size_t)(r0+1) * NP + c0)
                               : make_float2(0.f, 0.f);

    int s0 = 0, s1 = 0;
    size_t sb0 = (((size_t)(b*NP + c0))     * 32 + chunk) * SLOTS;
    size_t sb1 = (((size_t)(b*NP + c0 + 1)) * 32 + chunk) * SLOTS;
    for (int r = r0; r < r0 + 128; r++) {
        float um0 = __shfl_up_sync(0xffffffffu, pm1.y, 1);
        if (lane == 0)
            um0 = (r > 0 && c0 > 0) ? base[(size_t)(r-1) * NP + c0 - 1] : 0.f;
        float dp0 = (r < NP-1) ? pp1.y : 0.f;
        float um1v = (r > 0) ? pm1.x : 0.f;
        float dp1v = __shfl_down_sync(0xffffffffu, pp1.x, 1);
        if (lane == 31)
            dp1v = (r < NP-1 && c0 + 2 < NP) ? base[(size_t)(r+1) * NP + c0 + 2] : 0.f;

        float eqv = g_eq[r];
        float eqs = eqv * SCALEF;
        float l0 = (p0.x + um0 + dp0) * eqs;
        float l1 = (p0.y + um1v + dp1v) * eqs;
        if (l0 > lth0 && eqv != 0.f && s0 < SLOTS) {
            g_cidx[sb0 + s0] = r;
            g_cwgt[sb0 + s0] = expf(l0 - M0) * Si0 * eqv;
            s0++;
        }
        if (l1 > lth1 && eqv != 0.f && s1 < SLOTS) {
            g_cidx[sb1 + s1] = r;
            g_cwgt[sb1 + s1] = expf(l1 - M1) * Si1 * eqv;
            s1++;
        }
        pm1 = p0; p0 = pp1;
        pp1 = (r + 2 < NP) ? *(const float2*)(base + (size_t)(r+2) * NP + c0)
                           : make_float2(0.f, 0.f);
    }
    g_ccnt[(b*NP + c0)     * 32 + chunk] = s0;
    g_ccnt[(b*NP + c0 + 1) * 32 + chunk] = s1;
}

__global__ void k_merge() {
    int idx = blockIdx.x * blockDim.x + threadIdx.x;
    if (idx >= BT * NP) return;
    int cnt = 0;
    size_t ob = (size_t)idx * KMAX;
    for (int ch = 0; ch < 32; ch++) {
        int c = g_ccnt[idx * 32 + ch];
        size_t sb = (((size_t)idx) * 32 + ch) * SLOTS;
        for (int i = 0; i < c && cnt < KMAX; i++) {
            g_midx[ob + cnt] = g_cidx[sb + i];
            g_mwgt[ob + cnt] = g_cwgt[sb + i];
            cnt++;
        }
    }
    g_mcnt[idx] = cnt;
}

// ===================== sparse apply + transposed-conv gather ================
__global__ void k_apply() {
    int wid = threadIdx.x >> 5, lane = threadIdx.x & 31;
    int P = blockIdx.x * 8 + wid;
    int b = blockIdx.y;
    int Y = P >> 7, X = P & 127;
    const __half* bgc = g_bgcl + (size_t)b * HWF * CC;
    float4 acc = make_float4(0.f, 0.f, 0.f, 0.f);
#pragma unroll
    for (int di = 0; di < 4; di++) {
        int ty = Y + 1 - di;
        if (ty < 0 || (ty & 1)) continue;
        int my = ty >> 1;
        if (my >= HS) continue;
#pragma unroll
        for (int dj = 0; dj < 4; dj++) {
            int tx = X + 1 - dj;
            if (tx < 0 || (tx & 1)) continue;
            int mx = tx >> 1;
            if (mx >= HS) continue;
            int p = my * 64 + mx;
            int lb = b * NP + p;
            int cnt = g_mcnt[lb];
            const int*   il = g_midx + (size_t)lb * KMAX;
            const float* wl = g_mwgt + (size_t)lb * KMAX;
            for (int i = 0; i < cnt; i++) {
                int m = il[i];
                float w = wl[i];
                int miy = m >> 6, mix = m & 63;
                int Ys = 2*miy + di - 1, Xs = 2*mix + dj - 1;
                if ((unsigned)Ys >= HH || (unsigned)Xs >= WW) continue;
                union { uint2 u; __half2 h[2]; } v;
                v.u = *(const uint2*)(bgc + ((size_t)(Ys * WW + Xs)) * CC + lane * 4);
                float2 a0 = __half22float2(v.h[0]);
                float2 a1 = __half22float2(v.h[1]);
                acc.x += w * a0.x; acc.y += w * a0.y;
                acc.z += w * a1.x; acc.w += w * a1.y;
            }
        }
    }
    union { __half2 h[2]; uint2 u; } cv;
    cv.h[0] = __floats2half2_rn(acc.x * 0.25f, acc.y * 0.25f);
    cv.h[1] = __floats2half2_rn(acc.z * 0.25f, acc.w * 0.25f);
    *(uint2*)(g_y16 + ((size_t)b * HWF + P) * CC + lane * 4) = cv.u;
}

// ===================== host orchestration =====================
extern "C" void kernel_launch(void* const* d_in, const int* in_sizes, int n_in,
                              void* d_out, int out_size) {
    const float* fg   = (const float*)d_in[0];
    const float* bg   = (const float*)d_in[1];
    const float* mask = (const float*)d_in[2];
    const float* w1   = (const float*)d_in[3];
    const float* b1   = (const float*)d_in[4];
    const float* w2   = (const float*)d_in[5];
    const float* b2   = (const float*)d_in[6];
    float* out = (float*)d_out;

    cudaFuncSetAttribute(mgemm256, cudaFuncAttributeMaxDynamicSharedMemorySize, M2SMEM);
    cudaFuncSetAttribute(cgemm<0>, cudaFuncAttributeMaxDynamicSharedMemorySize, CGEMM_SMEM);
    cudaFuncSetAttribute(cgemm<1>, cudaFuncAttributeMaxDynamicSharedMemorySize, CGEMM_SMEM);

    __nv_bfloat16 *bh, *bl, *fh, *fl;
    __half *y16, *h16, *w116, *w216;
    float *bufA, *bufB;
    cudaGetSymbolAddress((void**)&bh, g_bh);     cudaGetSymbolAddress((void**)&bl, g_bl);
    cudaGetSymbolAddress((void**)&fh, g_fh);     cudaGetSymbolAddress((void**)&fl, g_fl);
    cudaGetSymbolAddress((void**)&y16, g_y16);   cudaGetSymbolAddress((void**)&h16, g_h16);
    cudaGetSymbolAddress((void**)&w116, g_w116); cudaGetSymbolAddress((void**)&w216, g_w216);
    cudaGetSymbolAddress((void**)&bufA, g_bufA);
    cudaGetSymbolAddress((void**)&bufB, g_bufB);

    // prep
    k_half    <<<(BT*NP*CC + 255)/256, 256>>>(bg, bh, bl);
    k_half    <<<(BT*NP*CC + 255)/256, 256>>>(fg, fh, fl);
    k_ss      <<<(BT*NP + 255)/256, 256>>>();
    k_inv     <<<(BT*NP + 255)/256, 256>>>();
    k_bgcl    <<<dim3(HWF/32, CC/32, BT), 256>>>(bg);
    k_eq      <<<16, 256>>>(mask);
    k_wreorder<<<(CC*K1 + 255)/256, 256>>>(w1, w116);
    k_wreorder<<<(CC*K1 + 255)/256, 256>>>(w2, w216);

    // GEMM1: G[u][v] = sum_c b[u][c] f[v][c]  (bf16 3-term, 128x256) -> bufA
    mgemm256<<<dim3(16, 32, BT), 256, M2SMEM>>>(
        bh, bl, fh, fl, bufA, CC, NP,
        (size_t)NP * CC, (size_t)NP * CC, (size_t)NP * NP);

    // scores = 9-tap diagonal stencil / norm -> bufB
    k_stencil9<<<BT * 4096, 256>>>(bufA, bufB);

    // fuse1 + permutation -> bufA
    k_fuseperm<<<BT * NP, 256>>>(bufB, bufA);

    // fuse2 on-the-fly + softmax stats (2 cols/thread)
    k_smax1<<<dim3(8, 32, BT), 256>>>(bufA);
    k_smax2<<<32, 256>>>();

    // sparse selection (2 cols/thread) + merge
    k_sel  <<<dim3(8, 32, BT), 256>>>(bufA);
    k_merge<<<32, 256>>>();

    // sparse attention apply + transposed-conv gather -> y16
    k_apply<<<dim3(HWF/8, BT), 256>>>();

    // conv1 + ELU (implicit, fp16 1-term W) -> h16 image
    cgemm<1><<<dim3(HWF/256, 1, BT), 256, CGEMM_SMEM>>>(
        w116, y16, nullptr, h16, b1);

    // conv2 + ELU (implicit) -> out fp32 NCHW
    cgemm<0><<<dim3(HWF/256, 1, BT), 256, CGEMM_SMEM>>>(
        w216, h16, out, nullptr, b2);
}

// round 17
// speedup vs baseline: 1.0721x; 1.0584x over previous
#include <cuda_runtime.h>
#include <cuda_bf16.h>
#include <cuda_fp16.h>
#include <math.h>
#include <stdint.h>

#define BT 2
#define CC 128
#define HH 128
#define WW 128
#define HS 64
#define NP 4096
#define K1 1152
#define HWF 16384
#define SCALEF 10.0f
#define SEL_THR 1e-7f
#define SLOTS 16
#define KMAX 128

// ===================== scratch =====================
__device__ __align__(256) __nv_bfloat16 g_bh [(size_t)BT*NP*CC];
__device__ __align__(256) __nv_bfloat16 g_bl [(size_t)BT*NP*CC];
__device__ __align__(256) __nv_bfloat16 g_fh [(size_t)BT*NP*CC];
__device__ __align__(256) __nv_bfloat16 g_fl [(size_t)BT*NP*CC];
__device__ __align__(256) __half        g_bgcl[(size_t)BT*HWF*CC]; // bg channels-last fp16
__device__ __align__(256) __half        g_y16 [(size_t)BT*HWF*CC]; // y image channels-last
__device__ __align__(256) __half        g_h16 [(size_t)BT*HWF*CC]; // h image channels-last
__device__ __align__(256) __half        g_w116[CC*K1];
__device__ __align__(256) __half        g_w216[CC*K1];
__device__ __align__(256) float g_bufA[(size_t)BT*NP*NP];
__device__ __align__(256) float g_bufB[(size_t)BT*NP*NP];
__device__ int   g_cidx[(size_t)BT*NP*32*SLOTS];
__device__ float g_cwgt[(size_t)BT*NP*32*SLOTS];
__device__ int   g_ccnt[BT*NP*32];
__device__ int   g_midx[(size_t)BT*NP*KMAX];
__device__ float g_mwgt[(size_t)BT*NP*KMAX];
__device__ int   g_mcnt[BT*NP];
__device__ float g_eq  [NP];
__device__ float g_ss  [BT*NP];
__device__ float g_inv [BT*NP];
__device__ float g_pmax[BT*32*NP];
__device__ float g_psum[BT*32*NP];
__device__ float g_cmax[BT*NP];
__device__ float g_csum[BT*NP];
__device__ float g_lthr[BT*NP];

__device__ __forceinline__ void split_store(__nv_bfloat16* H, __nv_bfloat16* L,
                                            size_t idx, float v) {
    __nv_bfloat16 h = __float2bfloat16(v);
    H[idx] = h;
    L[idx] = __float2bfloat16(v - __bfloat162float(h));
}
__device__ __forceinline__ uint32_t smem_u32(const void* p) {
    uint32_t a;
    asm("{ .reg .u64 t; cvta.to.shared.u64 t, %1; cvt.u32.u64 %0, t; }" : "=r"(a) : "l"(p));
    return a;
}
__device__ __forceinline__ void ldsm_x4(uint32_t (&r)[4], uint32_t addr) {
    asm volatile("ldmatrix.sync.aligned.m8n8.x4.shared.b16 {%0,%1,%2,%3}, [%4];"
                 : "=r"(r[0]), "=r"(r[1]), "=r"(r[2]), "=r"(r[3]) : "r"(addr));
}
__device__ __forceinline__ void mma_bf16(float (&d)[4], const uint32_t (&a)[4],
                                         uint32_t b0, uint32_t b1) {
    asm volatile("mma.sync.aligned.m16n8k16.row.col.f32.bf16.bf16.f32 "
        "{%0,%1,%2,%3}, {%4,%5,%6,%7}, {%8,%9}, {%0,%1,%2,%3};"
        : "+f"(d[0]), "+f"(d[1]), "+f"(d[2]), "+f"(d[3])
        : "r"(a[0]), "r"(a[1]), "r"(a[2]), "r"(a[3]), "r"(b0), "r"(b1));
}
__device__ __forceinline__ void mma_f16(float (&d)[4], const uint32_t (&a)[4],
                                        uint32_t b0, uint32_t b1) {
    asm volatile("mma.sync.aligned.m16n8k16.row.col.f32.f16.f16.f32 "
        "{%0,%1,%2,%3}, {%4,%5,%6,%7}, {%8,%9}, {%0,%1,%2,%3};"
        : "+f"(d[0]), "+f"(d[1]), "+f"(d[2]), "+f"(d[3])
        : "r"(a[0]), "r"(a[1]), "r"(a[2]), "r"(a[3]), "r"(b0), "r"(b1));
}
__device__ __forceinline__ void cpasync16(uint32_t saddr, const void* g) {
    asm volatile("cp.async.cg.shared.global [%0], [%1], 16;" :: "r"(saddr), "l"(g));
}
__device__ __forceinline__ void cpasync16z(uint32_t saddr, const void* g, int szbytes) {
    asm volatile("cp.async.cg.shared.global [%0], [%1], 16, %2;"
                 :: "r"(saddr), "l"(g), "r"(szbytes));
}

// ===================== prep =====================
__global__ void k_half(const float* __restrict__ src, __nv_bfloat16* H, __nv_bfloat16* L) {
    int idx = blockIdx.x * blockDim.x + threadIdx.x;
    if (idx >= BT * NP * CC) return;
    int c = idx & 127;
    int t = idx >> 7;
    int n = t & 4095;
    int b = t >> 12;
    int y = n >> 6, x = n & 63;
    float v = src[(((size_t)b*CC + c)*HH + 2*y)*WW + 2*x];
    split_store(H, L, (size_t)idx, v);
}

__global__ void k_ss() {
    int idx = blockIdx.x * blockDim.x + threadIdx.x;
    if (idx >= BT * NP) return;
    const __nv_bfloat162* h2 = (const __nv_bfloat162*)(g_bh + (size_t)idx * CC);
    const __nv_bfloat162* l2 = (const __nv_bfloat162*)(g_bl + (size_t)idx * CC);
    float s = 0.f;
#pragma unroll
    for (int c = 0; c < CC/2; c++) {
        float2 a = __bfloat1622float2(h2[c]);
        float2 bb = __bfloat1622float2(l2[c]);
        float v0 = a.x + bb.x, v1 = a.y + bb.y;
        s += v0*v0 + v1*v1;
    }
    g_ss[idx] = s;
}

__global__ void k_inv() {
    int idx = blockIdx.x * blockDim.x + threadIdx.x;
    if (idx >= BT * NP) return;
    int b = idx >> 12, n = idx & 4095;
    int ny = n >> 6, nx = n & 63;
    float s = 0.f;
#pragma unroll
    for (int i = 0; i < 3; i++)
#pragma unroll
        for (int j = 0; j < 3; j++) {
            int y = ny + i - 1, x = nx + j - 1;
            if ((unsigned)y < 64u && (unsigned)x < 64u)
                s += g_ss[b*NP + y*64 + x];
        }
    g_inv[idx] = 1.f / fmaxf(sqrtf(s), 1e-4f);
}

__global__ void k_bgcl(const float* __restrict__ bg) {
    __shared__ float tile[32][33];
    int b = blockIdx.z;
    int c0 = blockIdx.y * 32;
    int p0 = blockIdx.x * 32;
    int tx = threadIdx.x & 31, ty = threadIdx.x >> 5;
#pragma unroll
    for (int k = 0; k < 4; k++) {
        int c = c0 + ty + k*8;
        tile[ty + k*8][tx] = bg[((size_t)(b*CC + c))*HWF + p0 + tx];
    }
    __syncthreads();
#pragma unroll
    for (int k = 0; k < 4; k++) {
        int p = p0 + ty + k*8;
        g_bgcl[((size_t)(b*HWF + p))*CC + c0 + tx] = __float2half(tile[tx][ty + k*8]);
    }
}

__global__ void k_eq(const float* __restrict__ mask) {
    int n = blockIdx.x * blockDim.x + threadIdx.x;
    if (n >= NP) return;
    int ny = n / HS, nx = n % HS;
    float s = 0.f;
#pragma unroll
    for (int i = 0; i < 3; i++)
#pragma unroll
        for (int j = 0; j < 3; j++) {
            int y = ny + i - 1, x = nx + j - 1;
            if ((unsigned)y < HS && (unsigned)x < HS)
                s += mask[(2*y)*WW + 2*x];
        }
    g_eq[n] = ((s / 9.f) == 0.f) ? 1.f : 0.f;
}

// weight reorder: out[r][tap*128+c] = w[r][c*9+tap], single fp16
__global__ void k_wreorder(const float* __restrict__ w, __half* H) {
    int idx = blockIdx.x * blockDim.x + threadIdx.x;
    if (idx >= CC * K1) return;
    int r = idx / K1;
    int rem = idx % K1;
    int tap = rem >> 7;
    int c = rem & 127;
    H[idx] = __float2half(w[r * K1 + c * 9 + tap]);
}

// ===================== bf16-split GEMM1: 128m x 256n, 3-term ================
#define KT 32
#define STAGES 3
#define M2STAGE (8192*2 + 16384*2)
#define M2SMEM (STAGES*M2STAGE)

__global__ void __launch_bounds__(256, 1) mgemm256(
    const __nv_bfloat16* __restrict__ Ah, const __nv_bfloat16* __restrict__ Al,
    const __nv_bfloat16* __restrict__ Bh, const __nv_bfloat16* __restrict__ Bl,
    float* __restrict__ C, int K, int N,
    size_t sA, size_t sB, size_t sC)
{
    extern __shared__ char sm[];
    const uint32_t smb = smem_u32(sm);
    const int tid = threadIdx.x;
    const int bz = blockIdx.z;
    const int bm = blockIdx.y * 128;
    const int bn = blockIdx.x * 256;
    C += sC * bz;
    const __nv_bfloat16* ah = Ah + sA * bz;
    const __nv_bfloat16* al = Al + sA * bz;
    const __nv_bfloat16* bhp = Bh + sB * bz;
    const __nv_bfloat16* blp = Bl + sB * bz;

    const int NC = K >> 5;

    auto load_stage = [&](int s, int kc) {
#pragma unroll
        for (int it = 0; it < 2; it++) {
            int id = tid + it * 256;
            int row = id >> 2, ch = id & 3;
            uint32_t swz = (uint32_t)(row * 64 + ((ch ^ ((row >> 1) & 3)) << 4));
            cpasync16(smb + s*M2STAGE + swz,        ah + (size_t)(bm + row) * K + kc + ch * 8);
            cpasync16(smb + s*M2STAGE + 8192 + swz, al + (size_t)(bm + row) * K + kc + ch * 8);
        }
#pragma unroll
        for (int it = 0; it < 4; it++) {
            int id = tid + it * 256;
            int row = id >> 2, ch = id & 3;
            uint32_t swz = (uint32_t)(row * 64 + ((ch ^ ((row >> 1) & 3)) << 4));
            cpasync16(smb + s*M2STAGE + 16384 + swz, bhp + (size_t)(bn + row) * K + kc + ch * 8);
            cpasync16(smb + s*M2STAGE + 32768 + swz, blp + (size_t)(bn + row) * K + kc + ch * 8);
        }
        asm volatile("cp.async.commit_group;");
    };

#pragma unroll
    for (int s = 0; s < STAGES - 1; s++) load_stage(s, s * KT);

    const int wid = tid >> 5, lane = tid & 31;
    const int wm = wid & 1, wn = wid >> 1;

    float acc[4][8][4];
#pragma unroll
    for (int a = 0; a < 4; a++)
#pragma unroll
        for (int bb = 0; bb < 8; bb++)
#pragma unroll
            for (int c = 0; c < 4; c++) acc[a][bb][c] = 0.f;

    for (int i = 0; i < NC; i++) {
        asm volatile("cp.async.wait_group 1;");
        __syncthreads();

        if (i + STAGES - 1 < NC)
            load_stage((i + STAGES - 1) % STAGES, (i + STAGES - 1) * KT);
        else
            asm volatile("cp.async.commit_group;");

        const uint32_t stb = smb + (i % STAGES) * M2STAGE;
#pragma unroll
        for (int h = 0; h < 2; h++) {
            uint32_t ar[4][4], alr[4][4];
            uint32_t bh2[8][2], bl2[8][2];
#pragma unroll
            for (int tm = 0; tm < 4; tm++) {
                int row = wm*64 + tm*16 + (lane & 15);
                int ch  = 2*h + (lane >> 4);
                uint32_t ad = stb + row*64 + ((ch ^ ((row >> 1) & 3)) << 4);
                ldsm_x4(ar[tm], ad);
                ldsm_x4(alr[tm], ad + 8192);
            }
#pragma unroll
            for (int tb = 0; tb < 4; tb++) {
                int row = wn*64 + tb*16 + ((lane >> 4) << 3) + (lane & 7);
                int ch  = 2*h + ((lane >> 3) & 1);
                uint32_t bd = stb + 16384 + row*64 + ((ch ^ ((row >> 1) & 3)) << 4);
                uint32_t r[4];
                ldsm_x4(r, bd);
                bh2[tb*2][0] = r[0]; bh2[tb*2][1] = r[1];
                bh2[tb*2+1][0] = r[2]; bh2[tb*2+1][1] = r[3];
                ldsm_x4(r, bd + 16384);
                bl2[tb*2][0] = r[0]; bl2[tb*2][1] = r[1];
                bl2[tb*2+1][0] = r[2]; bl2[tb*2+1][1] = r[3];
            }
#pragma unroll
            for (int tm = 0; tm < 4; tm++)
#pragma unroll
                for (int tn = 0; tn < 8; tn++) {
                    mma_bf16(acc[tm][tn], ar[tm], bh2[tn][0], bh2[tn][1]);
                    mma_bf16(acc[tm][tn], ar[tm], bl2[tn][0], bl2[tn][1]);
                    mma_bf16(acc[tm][tn], alr[tm], bh2[tn][0], bh2[tn][1]);
                }
        }
    }

#pragma unroll
    for (int tm = 0; tm < 4; tm++) {
        int row = bm + wm*64 + tm*16 + (lane >> 2);
#pragma unroll
        for (int hf = 0; hf < 2; hf++) {
            int r = row + hf*8;
            float* dst = C + (size_t)r * N + bn + wn*64 + (lane & 3)*2;
#pragma unroll
            for (int tn = 0; tn < 8; tn++)
                *(float2*)(dst + tn*8) = make_float2(acc[tm][tn][hf*2+0], acc[tm][tn][hf*2+1]);
        }
    }
}

// ===================== implicit conv GEMM: 128ch x 256pix, fp16 1-term W =====
#define CSTAGE (8192 + 16384)
#define CGEMM_SMEM (STAGES*CSTAGE)
#define TPITCH 136

template<int OUT16>
__global__ void __launch_bounds__(256, 1) cgemm(
    const __half* __restrict__ Wh,
    const __half* __restrict__ img,
    float* __restrict__ Cout, __half* __restrict__ out16,
    const float* __restrict__ bias)
{
    extern __shared__ char sm[];
    const uint32_t smb = smem_u32(sm);
    const int tid = threadIdx.x;
    const int bz = blockIdx.z;
    const int bn = blockIdx.x * 256;
    const __half* ib = img + (size_t)bz * HWF * CC;

    const int NC = K1 >> 5;   // 36

    auto load_stage = [&](int s, int kc) {
#pragma unroll
        for (int it = 0; it < 2; it++) {
            int id = tid + it * 256;
            int row = id >> 2, ch = id & 3;
            uint32_t swz = (uint32_t)(row * 64 + ((ch ^ ((row >> 1) & 3)) << 4));
            cpasync16(smb + s*CSTAGE + swz, Wh + (size_t)row * K1 + kc + ch * 8);
        }
        int tap = kc >> 7;
        int ki = tap / 3, kj = tap - ki * 3;
        int c0 = kc & 127;
#pragma unroll
        for (int it = 0; it < 4; it++) {
            int id = tid + it * 256;
            int row = id >> 2, ch = id & 3;
            int p = bn + row;
            int Y = (p >> 7) + ki - 1, X = (p & 127) + kj - 1;
            bool ok = (unsigned)Y < HH && (unsigned)X < WW;
            const __half* g = ok ? ib + ((size_t)(Y * WW + X)) * CC + c0 + ch * 8 : ib;
            uint32_t swz = (uint32_t)(row * 64 + ((ch ^ ((row >> 1) & 3)) << 4));
            cpasync16z(smb + s*CSTAGE + 8192 + swz, g, ok ? 16 : 0);
        }
        asm volatile("cp.async.commit_group;");
    };

#pragma unroll
    for (int s = 0; s < STAGES - 1; s++) load_stage(s, s * KT);

    const int wid = tid >> 5, lane = tid & 31;
    const int wm = wid & 1, wn = wid >> 1;

    float acc[4][8][4];
#pragma unroll
    for (int a = 0; a < 4; a++)
#pragma unroll
        for (int bb = 0; bb < 8; bb++)
#pragma unroll
            for (int c = 0; c < 4; c++) acc[a][bb][c] = 0.f;

    for (int i = 0; i < NC; i++) {
        asm volatile("cp.async.wait_group 1;");
        __syncthreads();

        if (i + STAGES - 1 < NC)
            load_stage((i + STAGES - 1) % STAGES, (i + STAGES - 1) * KT);
        else
            asm volatile("cp.async.commit_group;");

        const uint32_t stb = smb + (i % STAGES) * CSTAGE;
#pragma unroll
        for (int h = 0; h < 2; h++) {
            uint32_t ah[4][4];
            uint32_t bf[8][2];
#pragma unroll
            for (int tm = 0; tm < 4; tm++) {
                int row = wm*64 + tm*16 + (lane & 15);
                int ch  = 2*h + (lane >> 4);
                uint32_t ad = stb + row*64 + ((ch ^ ((row >> 1) & 3)) << 4);
                ldsm_x4(ah[tm], ad);
            }
#pragma unroll
            for (int tb = 0; tb < 4; tb++) {
                int row = wn*64 + tb*16 + ((lane >> 4) << 3) + (lane & 7);
                int ch  = 2*h + ((lane >> 3) & 1);
                uint32_t bd = stb + 8192 + row*64 + ((ch ^ ((row >> 1) & 3)) << 4);
                uint32_t r[4];
                ldsm_x4(r, bd);
                bf[tb*2][0] = r[0]; bf[tb*2][1] = r[1];
                bf[tb*2+1][0] = r[2]; bf[tb*2+1][1] = r[3];
            }
#pragma unroll
            for (int tm = 0; tm < 4; tm++)
#pragma unroll
                for (int tn = 0; tn < 8; tn++)
                    mma_f16(acc[tm][tn], ah[tm], bf[tn][0], bf[tn][1]);
        }
    }

    if (OUT16) {
        asm volatile("cp.async.wait_group 0;");
        __syncthreads();
        __half* st = (__half*)sm;
#pragma unroll
        for (int tm = 0; tm < 4; tm++) {
#pragma unroll
            for (int hf = 0; hf < 2; hf++) {
                int r = wm*64 + tm*16 + (lane >> 2) + hf*8;
                float bv = bias[r];
#pragma unroll
                for (int tn = 0; tn < 8; tn++) {
                    int col = wn*64 + tn*8 + (lane & 3)*2;
                    float x0 = acc[tm][tn][hf*2+0] + bv;
                    float x1 = acc[tm][tn][hf*2+1] + bv;
                    x0 = x0 > 0.f ? x0 : expf(x0) - 1.f;
                    x1 = x1 > 0.f ? x1 : expf(x1) - 1.f;
                    st[(size_t)col * TPITCH + r]       = __float2half(x0);
                    st[(size_t)(col+1) * TPITCH + r]   = __float2half(x1);
                }
            }
        }
        __syncthreads();
        __half* dst = out16 + ((size_t)bz * HWF + bn + tid) * CC;
        const uint4* srcv = (const uint4*)(st + (size_t)tid * TPITCH);
#pragma unroll
        for (int i = 0; i < 16; i++)
            ((uint4*)dst)[i] = srcv[i];
    } else {
        float* C = Cout + (size_t)bz * CC * HWF;
#pragma unroll
        for (int tm = 0; tm < 4; tm++) {
            int row = wm*64 + tm*16 + (lane >> 2);
#pragma unroll
            for (int hf = 0; hf < 2; hf++) {
                int r = row + hf*8;
                float bv = bias[r];
                float* dst = C + (size_t)r * HWF + bn + wn*64 + (lane & 3)*2;
#pragma unroll
                for (int tn = 0; tn < 8; tn++) {
                    float x0 = acc[tm][tn][hf*2+0] + bv;
                    float x1 = acc[tm][tn][hf*2+1] + bv;
                    x0 = x0 > 0.f ? x0 : expf(x0) - 1.f;
                    x1 = x1 > 0.f ? x1 : expf(x1) - 1.f;
                    *(float2*)(dst + tn*8) = make_float2(x0, x1);
                }
            }
        }
    }
}

// ===================== stencil =====================
__global__ void __launch_bounds__(256) k_stencil9(const float* __restrict__ G,
                                                  float* __restrict__ out) {
    __shared__ float t3[3][64][64];
    int bid = blockIdx.x;
    int b = bid >> 12;
    int rest = bid & 4095;
    int ny = rest >> 6, py = rest & 63;
    const float* Gb = G + (size_t)b * NP * NP;
    float* ob = out + (size_t)b * NP * NP;
    int tid = threadIdx.x;

#pragma unroll
    for (int dy = 0; dy < 3; dy++) {
        int gy = ny + dy - 1, gpy = py + dy - 1;
        bool ok = (unsigned)gy < 64 && (unsigned)gpy < 64;
        for (int idx = tid; idx < 4096; idx += 256) {
            int i = idx >> 6, jj = idx & 63;
            t3[dy][i][jj] = ok ? Gb[((size_t)(gy*64 + i)) * NP + gpy*64 + jj] : 0.f;
        }
    }
    __syncthreads();

    int px = tid & 63;
    int nx0 = tid >> 6;
    for (int nx = nx0; nx < 64; nx += 4) {
        float s = 0.f;
#pragma unroll
        for (int dy = 0; dy < 3; dy++)
#pragma unroll
            for (int dx = -1; dx <= 1; dx++) {
                int a = nx + dx, c = px + dx;
                if ((unsigned)a < 64 && (unsigned)c < 64)
                    s += t3[dy][a][c];
            }
        ob[((size_t)(ny*64 + nx)) * NP + py*64 + px] = s * g_inv[b*NP + ny*64 + nx];
    }
}

// ===================== fuse1 + permutation =====================
__global__ void k_fuseperm(const float* __restrict__ in, float* __restrict__ out) {
    __shared__ float tile[64 * 65];
    int brow = blockIdx.x;
    int b = brow / NP, rp = brow % NP;
    int nx = rp >> 6, ny = rp & 63;
    int r = ny * 64 + nx;
    const float* src = in + (size_t)b * NP * NP;
    float*       dst = out + ((size_t)b * NP + rp) * NP;
    int tid = threadIdx.x;
    for (int k = tid; k < NP; k += 256) {
        float f = src[(size_t)r * NP + k];
        if (r > 0 && k > 0)           f += src[(size_t)(r-1) * NP + k - 1];
        if (r < NP-1 && k < NP-1)     f += src[(size_t)(r+1) * NP + k + 1];
        tile[(k & 63) * 65 + (k >> 6)] = f;
    }
    __syncthreads();
    for (int j = tid; j < NP; j += 256)
        dst[j] = tile[(j >> 6) * 65 + (j & 63)];
}

// ===================== softmax stats (fuse2 on the fly) =====================
__global__ void k_smax1(const float* __restrict__ in) {
    int col = blockIdx.x * 256 + threadIdx.x;
    int chunk = blockIdx.y;
    int b = blockIdx.z;
    int lane = threadIdx.x & 31;
    const float* base = in + (size_t)b * NP * NP;
    int r0 = chunk * 128;

    float pm1 = (r0 > 0) ? base[(size_t)(r0-1) * NP + col] : 0.f;
    float p0  = base[(size_t)r0 * NP + col];
    float pp1 = (r0 + 1 < NP) ? base[(size_t)(r0+1) * NP + col] : 0.f;

    float mx = -1e30f, sm = 0.f;
    for (int r = r0; r < r0 + 128; r++) {
        float um1 = __shfl_up_sync(0xffffffffu, pm1, 1);
        if (lane == 0)
            um1 = (r > 0 && col > 0) ? base[(size_t)(r-1) * NP + col - 1] : 0.f;
        float dp1 = __shfl_down_sync(0xffffffffu, pp1, 1);
        if (lane == 31)
            dp1 = (r < NP-1 && col < NP-1) ? base[(size_t)(r+1) * NP + col + 1] : 0.f;
        float v = p0 + um1 + dp1;
        float l = v * (g_eq[r] * SCALEF);
        if (l > mx) { sm = sm * expf(mx - l) + 1.f; mx = l; }
        else        { sm += expf(l - mx); }
        pm1 = p0; p0 = pp1;
        pp1 = (r + 2 < NP) ? base[(size_t)(r+2) * NP + col] : 0.f;
    }
    g_pmax[((size_t)b * 32 + chunk) * NP + col] = mx;
    g_psum[((size_t)b * 32 + chunk) * NP + col] = sm;
}

__global__ void k_smax2() {
    int idx = blockIdx.x * blockDim.x + threadIdx.x;
    if (idx >= BT * NP) return;
    int b = idx / NP, col = idx % NP;
    float M = -1e30f;
    for (int i = 0; i < 32; i++)
        M = fmaxf(M, g_pmax[((size_t)b * 32 + i) * NP + col]);
    float S = 0.f;
    for (int i = 0; i < 32; i++)
        S += g_psum[((size_t)b * 32 + i) * NP + col] *
             expf(g_pmax[((size_t)b * 32 + i) * NP + col] - M);
    g_cmax[idx] = M;
    g_csum[idx] = S;
    g_lthr[idx] = M + logf(SEL_THR * S);
}

// ===================== sparse selection (R10 exact) =========================
__global__ void k_sel(const float* __restrict__ in) {
    int col = blockIdx.x * 256 + threadIdx.x;    // p
    int chunk = blockIdx.y;
    int b = blockIdx.z;
    int lane = threadIdx.x & 31;
    const float* base = in + (size_t)b * NP * NP;
    int r0 = chunk * 128;

    float lth = g_lthr[b*NP + col];
    float M   = g_cmax[b*NP + col];
    float Sin = 1.f / g_csum[b*NP + col];

    float pm1 = (r0 > 0) ? base[(size_t)(r0-1) * NP + col] : 0.f;
    float p0  = base[(size_t)r0 * NP + col];
    float pp1 = (r0 + 1 < NP) ? base[(size_t)(r0+1) * NP + col] : 0.f;

    int s = 0;
    size_t slotbase = (((size_t)(b*NP + col)) * 32 + chunk) * SLOTS;
    for (int r = r0; r < r0 + 128; r++) {
        float um1 = __shfl_up_sync(0xffffffffu, pm1, 1);
        if (lane == 0)
            um1 = (r > 0 && col > 0) ? base[(size_t)(r-1) * NP + col - 1] : 0.f;
        float dp1 = __shfl_down_sync(0xffffffffu, pp1, 1);
        if (lane == 31)
            dp1 = (r < NP-1 && col < NP-1) ? base[(size_t)(r+1) * NP + col + 1] : 0.f;
        float v = p0 + um1 + dp1;
        float eqv = g_eq[r];
        float l = v * (eqv * SCALEF);
        if (l > lth && eqv != 0.f && s < SLOTS) {
            g_cidx[slotbase + s] = r;
            g_cwgt[slotbase + s] = expf(l - M) * Sin * eqv;
            s++;
        }
        pm1 = p0; p0 = pp1;
        pp1 = (r + 2 < NP) ? base[(size_t)(r+2) * NP + col] : 0.f;
    }
    g_ccnt[(b*NP + col) * 32 + chunk] = s;
}

__global__ void k_merge() {
    int idx = blockIdx.x * blockDim.x + threadIdx.x;
    if (idx >= BT * NP) return;
    int cnt = 0;
    size_t ob = (size_t)idx * KMAX;
    for (int ch = 0; ch < 32; ch++) {
        int c = g_ccnt[idx * 32 + ch];
        size_t sb = (((size_t)idx) * 32 + ch) * SLOTS;
        for (int i = 0; i < c && cnt < KMAX; i++) {
            g_midx[ob + cnt] = g_cidx[sb + i];
            g_mwgt[ob + cnt] = g_cwgt[sb + i];
            cnt++;
        }
    }
    g_mcnt[idx] = cnt;
}

// ===================== sparse apply + transposed-conv gather ================
__global__ void k_apply() {
    int wid = threadIdx.x >> 5, lane = threadIdx.x & 31;
    int P = blockIdx.x * 8 + wid;
    int b = blockIdx.y;
    int Y = P >> 7, X = P & 127;
    const __half* bgc = g_bgcl + (size_t)b * HWF * CC;
    float4 acc = make_float4(0.f, 0.f, 0.f, 0.f);
#pragma unroll
    for (int di = 0; di < 4; di++) {
        int ty = Y + 1 - di;
        if (ty < 0 || (ty & 1)) continue;
        int my = ty >> 1;
        if (my >= HS) continue;
#pragma unroll
        for (int dj = 0; dj < 4; dj++) {
            int tx = X + 1 - dj;
            if (tx < 0 || (tx & 1)) continue;
            int mx = tx >> 1;
            if (mx >= HS) continue;
            int p = my * 64 + mx;
            int lb = b * NP + p;
            int cnt = g_mcnt[lb];
            const int*   il = g_midx + (size_t)lb * KMAX;
            const float* wl = g_mwgt + (size_t)lb * KMAX;
            for (int i = 0; i < cnt; i++) {
                int m = il[i];
                float w = wl[i];
                int miy = m >> 6, mix = m & 63;
                int Ys = 2*miy + di - 1, Xs = 2*mix + dj - 1;
                if ((unsigned)Ys >= HH || (unsigned)Xs >= WW) continue;
                union { uint2 u; __half2 h[2]; } v;
                v.u = *(const uint2*)(bgc + ((size_t)(Ys * WW + Xs)) * CC + lane * 4);
                float2 a0 = __half22float2(v.h[0]);
                float2 a1 = __half22float2(v.h[1]);
                acc.x += w * a0.x; acc.y += w * a0.y;
                acc.z += w * a1.x; acc.w += w * a1.y;
            }
        }
    }
    union { __half2 h[2]; uint2 u; } cv;
    cv.h[0] = __floats2half2_rn(acc.x * 0.25f, acc.y * 0.25f);
    cv.h[1] = __floats2half2_rn(acc.z * 0.25f, acc.w * 0.25f);
    *(uint2*)(g_y16 + ((size_t)b * HWF + P) * CC + lane * 4) = cv.u;
}

// ===================== host orchestration =====================
extern "C" void kernel_launch(void* const* d_in, const int* in_sizes, int n_in,
                              void* d_out, int out_size) {
    const float* fg   = (const float*)d_in[0];
    const float* bg   = (const float*)d_in[1];
    const float* mask = (const float*)d_in[2];
    const float* w1   = (const float*)d_in[3];
    const float* b1   = (const float*)d_in[4];
    const float* w2   = (const float*)d_in[5];
    const float* b2   = (const float*)d_in[6];
    float* out = (float*)d_out;

    cudaFuncSetAttribute(mgemm256, cudaFuncAttributeMaxDynamicSharedMemorySize, M2SMEM);
    cudaFuncSetAttribute(cgemm<0>, cudaFuncAttributeMaxDynamicSharedMemorySize, CGEMM_SMEM);
    cudaFuncSetAttribute(cgemm<1>, cudaFuncAttributeMaxDynamicSharedMemorySize, CGEMM_SMEM);

    __nv_bfloat16 *bh, *bl, *fh, *fl;
    __half *y16, *h16, *w116, *w216;
    float *bufA, *bufB;
    cudaGetSymbolAddress((void**)&bh, g_bh);     cudaGetSymbolAddress((void**)&bl, g_bl);
    cudaGetSymbolAddress((void**)&fh, g_fh);     cudaGetSymbolAddress((void**)&fl, g_fl);
    cudaGetSymbolAddress((void**)&y16, g_y16);   cudaGetSymbolAddress((void**)&h16, g_h16);
    cudaGetSymbolAddress((void**)&w116, g_w116); cudaGetSymbolAddress((void**)&w216, g_w216);
    cudaGetSymbolAddress((void**)&bufA, g_bufA);
    cudaGetSymbolAddress((void**)&bufB, g_bufB);

    // prep
    k_half    <<<(BT*NP*CC + 255)/256, 256>>>(bg, bh, bl);
    k_half    <<<(BT*NP*CC + 255)/256, 256>>>(fg, fh, fl);
    k_ss      <<<(BT*NP + 255)/256, 256>>>();
    k_inv     <<<(BT*NP + 255)/256, 256>>>();
    k_bgcl    <<<dim3(HWF/32, CC/32, BT), 256>>>(bg);
    k_eq      <<<16, 256>>>(mask);
    k_wreorder<<<(CC*K1 + 255)/256, 256>>>(w1, w116);
    k_wreorder<<<(CC*K1 + 255)/256, 256>>>(w2, w216);

    // GEMM1: G[u][v] = sum_c b[u][c] f[v][c]  (bf16 3-term, 128x256) -> bufA
    mgemm256<<<dim3(16, 32, BT), 256, M2SMEM>>>(
        bh, bl, fh, fl, bufA, CC, NP,
        (size_t)NP * CC, (size_t)NP * CC, (size_t)NP * NP);

    // scores = 9-tap diagonal stencil / norm -> bufB
    k_stencil9<<<BT * 4096, 256>>>(bufA, bufB);

    // fuse1 + permutation -> bufA
    k_fuseperm<<<BT * NP, 256>>>(bufB, bufA);

    // fuse2 on-the-fly + softmax stats
    k_smax1<<<dim3(16, 32, BT), 256>>>(bufA);
    k_smax2<<<32, 256>>>();

    // sparse selection + merge
    k_sel  <<<dim3(16, 32, BT), 256>>>(bufA);
    k_merge<<<32, 256>>>();

    // sparse attention apply + transposed-conv gather -> y16
    k_apply<<<dim3(HWF/8, BT), 256>>>();

    // conv1 + ELU (implicit, fp16 1-term W) -> h16 image
    cgemm<1><<<dim3(HWF/256, 1, BT), 256, CGEMM_SMEM>>>(
        w116, y16, nullptr, h16, b1);

    // conv2 + ELU (implicit) -> out fp32 NCHW
    cgemm<0><<<dim3(HWF/256, 1, BT), 256, CGEMM_SMEM>>>(
        w216, h16, out, nullptr, b2);
}